// round 5
// baseline (speedup 1.0000x reference)
#include <cuda_runtime.h>
#include <math.h>

#define IMG_H 2048
#define IMG_W 2048
#define NB 4
#define OUT_DIM 2038          // IMG - 10 (VALID 11x11)
#define TILE_O 32
#define TILE_I 42             // TILE_O + 10
#define SPITCH 45             // odd pitch -> conflict-free row-strided access
#define HPITCH 33             // pitch for hconv arrays (33*r+c conflict-free)

// ---------------- global accumulators (zeroed by init kernel each launch) ---
__device__ double g_l1, g_gh, g_gw, g_range, g_ssim;
__device__ double g_sp[NB], g_st[NB], g_spp[NB], g_stt[NB];
__device__ unsigned long long g_mse[NB];

struct Wt { float w[11]; };

__device__ __forceinline__ float quant255(float x) {
    // exact replica of reference _to_uint8_float (fp32 op-for-op)
    x = fminf(fmaxf(x, -1.0f), 1.0f);
    float x01 = fminf(fmaxf((x + 1.0f) * 0.5f, 0.0f), 1.0f);
    return floorf(fminf(fmaxf(x01 * 255.0f, 0.0f), 255.0f));
}

__global__ void loss_init() {
    int t = threadIdx.x;
    if (t == 0) { g_l1 = 0.0; g_gh = 0.0; g_gw = 0.0; g_range = 0.0; g_ssim = 0.0; }
    if (t < NB) { g_sp[t] = 0.0; g_st[t] = 0.0; g_spp[t] = 0.0; g_stt[t] = 0.0; g_mse[t] = 0ull; }
}

__global__ __launch_bounds__(256) void loss_main(const float* __restrict__ pred,
                                                 const float* __restrict__ targ,
                                                 Wt wp)
{
    __shared__ float sP[TILE_I * SPITCH];
    __shared__ float sT[TILE_I * SPITCH];
    __shared__ float hAll[5 * TILE_I * HPITCH];   // hP,hT,hPP,hTT,hPT
    __shared__ float s_redf[8][10];
    __shared__ unsigned s_redu[8];

    const int tid = threadIdx.x;
    const int b   = blockIdx.z;
    const int by0 = blockIdx.y * TILE_O;
    const int bx0 = blockIdx.x * TILE_O;
    const size_t ioff = (size_t)b * IMG_H * IMG_W;
    const float* P = pred + ioff;
    const float* T = targ + ioff;

    float wt[11];
    #pragma unroll
    for (int i = 0; i < 11; i++) wt[i] = wp.w[i];

    // ---- Phase A: load raw tile (OOB -> 0, only feeds invalid outputs) ----
    for (int i = tid; i < TILE_I * TILE_I; i += 256) {
        int r = i / TILE_I, c = i - r * TILE_I;
        int gy = by0 + r, gx = bx0 + c;
        float p = 0.f, t = 0.f;
        if (gy < IMG_H && gx < IMG_W) {
            size_t gi = (size_t)gy * IMG_W + gx;
            p = P[gi];
            t = T[gi];
        }
        sP[r * SPITCH + c] = p;
        sT[r * SPITCH + c] = t;
    }
    __syncthreads();

    // ---- Phase B: per-pixel reductions over the owned 32x32 region --------
    float a_l1 = 0.f, a_gh = 0.f, a_gw = 0.f, a_rng = 0.f;
    float a_sp = 0.f, a_st = 0.f, a_spp = 0.f, a_stt = 0.f, a_ssim = 0.f;
    unsigned a_mse = 0u;
    #pragma unroll
    for (int it = 0; it < 4; it++) {
        int i = tid + it * 256;           // 0..1023
        int ly = i >> 5, lx = i & 31;
        float p = sP[ly * SPITCH + lx];
        float t = sT[ly * SPITCH + lx];
        a_l1  += fabsf(p - t);
        a_rng += fmaxf(fabsf(p) - 1.0f, 0.0f);
        a_sp  += p;  a_st  += t;
        a_spp += p * p;  a_stt += t * t;
        if (by0 + ly < IMG_H - 1) {
            a_gh += fabsf((p - sP[(ly + 1) * SPITCH + lx]) - (t - sT[(ly + 1) * SPITCH + lx]));
        }
        if (bx0 + lx < IMG_W - 1) {
            a_gw += fabsf((p - sP[ly * SPITCH + lx + 1]) - (t - sT[ly * SPITCH + lx + 1]));
        }
        float qp = quant255(p), qt = quant255(t);
        float d = qp - qt;                 // integer-valued
        a_mse += (unsigned)(d * d);        // exact (<= 65025)
    }
    __syncthreads();

    // ---- Phase C: quantize tile in place ----------------------------------
    for (int i = tid; i < TILE_I * TILE_I; i += 256) {
        int r = i / TILE_I, c = i - r * TILE_I;
        int idx = r * SPITCH + c;
        sP[idx] = quant255(sP[idx]);
        sT[idx] = quant255(sT[idx]);
    }
    __syncthreads();

    // ---- Phase D: horizontal 11-tap conv, 5 fields x 42 rows --------------
    // sliding register window: 42 loads -> 32 outputs per (field,row)
    if (tid < 5 * TILE_I) {
        int field = tid / TILE_I;          // 0:P 1:T 2:PP 3:TT 4:PT
        int row   = tid - field * TILE_I;
        const float* a  = (field == 1 || field == 3) ? (sT + row * SPITCH) : (sP + row * SPITCH);
        const float* bs = (field == 4) ? (sT + row * SPITCH) : a;
        const bool sq  = (field == 2 || field == 3);
        const bool mul = (field == 4);
        float* dst = hAll + field * (TILE_I * HPITCH) + row * HPITCH;

        float buf[11];
        #pragma unroll
        for (int j = 0; j < 10; j++) {
            float v = a[j];
            buf[j] = sq ? v * v : (mul ? v * bs[j] : v);
        }
        #pragma unroll
        for (int oc = 0; oc < 32; oc++) {
            float v = a[oc + 10];
            buf[(oc + 10) % 11] = sq ? v * v : (mul ? v * bs[oc + 10] : v);
            float acc = 0.f;
            #pragma unroll
            for (int k = 0; k < 11; k++) acc = fmaf(wt[k], buf[(oc + k) % 11], acc);
            dst[oc] = acc;
        }
    }
    __syncthreads();

    // ---- Phase E: vertical 11-tap conv + SSIM map -------------------------
    // 128 threads: (tx, group of 8 output rows), sliding window per field
    const float C1F = 6.5025f;    // (0.01*255)^2
    const float C2F = 58.5225f;   // (0.03*255)^2
    if (tid < 128) {
        int tx  = tid & 31;
        int grp = tid >> 5;
        int rbase = grp * 8;
        float bv[5][11];
        #pragma unroll
        for (int f = 0; f < 5; f++) {
            #pragma unroll
            for (int j = 0; j < 10; j++)
                bv[f][j] = hAll[f * (TILE_I * HPITCH) + (rbase + j) * HPITCH + tx];
        }
        #pragma unroll
        for (int r = 0; r < 8; r++) {
            int lrow = rbase + r + 10;
            #pragma unroll
            for (int f = 0; f < 5; f++)
                bv[f][(r + 10) % 11] = hAll[f * (TILE_I * HPITCH) + lrow * HPITCH + tx];
            float m1 = 0.f, m2 = 0.f, cpp = 0.f, ctt = 0.f, cpt = 0.f;
            #pragma unroll
            for (int k = 0; k < 11; k++) {
                int idx = (r + k) % 11;
                float wk = wt[k];
                m1  = fmaf(wk, bv[0][idx], m1);
                m2  = fmaf(wk, bv[1][idx], m2);
                cpp = fmaf(wk, bv[2][idx], cpp);
                ctt = fmaf(wk, bv[3][idx], ctt);
                cpt = fmaf(wk, bv[4][idx], cpt);
            }
            if (by0 + rbase + r < OUT_DIM && bx0 + tx < OUT_DIM) {
                float m1s = m1 * m1, m2s = m2 * m2, m12 = m1 * m2;
                float s1 = cpp - m1s, s2 = ctt - m2s, s12 = cpt - m12;
                float num = (2.0f * m12 + C1F) * (2.0f * s12 + C2F);
                float den = (m1s + m2s + C1F) * (s1 + s2 + C2F);
                a_ssim += num / den;
            }
        }
    }

    // ---- Phase F: block reduction + atomics -------------------------------
    float vals[9] = {a_l1, a_gh, a_gw, a_rng, a_sp, a_st, a_spp, a_stt, a_ssim};
    #pragma unroll
    for (int q = 0; q < 9; q++) {
        float v = vals[q];
        #pragma unroll
        for (int o = 16; o > 0; o >>= 1) v += __shfl_down_sync(0xffffffffu, v, o);
        vals[q] = v;
    }
    unsigned mm = a_mse;
    #pragma unroll
    for (int o = 16; o > 0; o >>= 1) mm += __shfl_down_sync(0xffffffffu, mm, o);

    int wid = tid >> 5, lane = tid & 31;
    if (lane == 0) {
        #pragma unroll
        for (int q = 0; q < 9; q++) s_redf[wid][q] = vals[q];
        s_redu[wid] = mm;
    }
    __syncthreads();
    if (tid < 32) {
        float v[9];
        #pragma unroll
        for (int q = 0; q < 9; q++) {
            float x = (tid < 8) ? s_redf[tid][q] : 0.f;
            #pragma unroll
            for (int o = 4; o > 0; o >>= 1) x += __shfl_down_sync(0xffffffffu, x, o);
            v[q] = x;
        }
        unsigned xm = (tid < 8) ? s_redu[tid] : 0u;
        #pragma unroll
        for (int o = 4; o > 0; o >>= 1) xm += __shfl_down_sync(0xffffffffu, xm, o);
        if (tid == 0) {
            atomicAdd(&g_l1,    (double)v[0]);
            atomicAdd(&g_gh,    (double)v[1]);
            atomicAdd(&g_gw,    (double)v[2]);
            atomicAdd(&g_range, (double)v[3]);
            atomicAdd(&g_sp[b], (double)v[4]);
            atomicAdd(&g_st[b], (double)v[5]);
            atomicAdd(&g_spp[b],(double)v[6]);
            atomicAdd(&g_stt[b],(double)v[7]);
            atomicAdd(&g_ssim,  (double)v[8]);
            atomicAdd(&g_mse[b], (unsigned long long)xm);
        }
    }
}

__global__ void loss_final(float* __restrict__ out) {
    const double n = (double)IMG_H * (double)IMG_W;
    double l1 = g_l1 / ((double)NB * n);
    double grad = g_gh / ((double)NB * (double)(IMG_H - 1) * (double)IMG_W)
                + g_gw / ((double)NB * (double)IMG_H * (double)(IMG_W - 1));
    double energy = 0.0, dist = 0.0, psnr = 0.0;
    for (int i = 0; i < NB; i++) {
        double pm = g_sp[i] / n, tm = g_st[i] / n;
        energy += (pm - tm) * (pm - tm);
        double ps = sqrt(fmax((g_spp[i] - n * pm * pm) / (n - 1.0), 0.0));
        double ts = sqrt(fmax((g_stt[i] - n * tm * tm) / (n - 1.0), 0.0));
        dist += (ps - ts) * (ps - ts);
        double mse = (double)g_mse[i] / n;
        psnr += (mse == 0.0) ? 100.0 : 10.0 * log10(65025.0 / mse);
    }
    energy /= NB; dist /= NB; psnr /= NB;
    double range = g_range / ((double)NB * n);
    double phys = energy + 0.5 * dist + 0.1 * range;
    double ssim_mean = g_ssim / ((double)NB * (double)OUT_DIM * (double)OUT_DIM);
    ssim_mean = fmin(fmax(ssim_mean, 0.0), 1.0);
    double total = 1.0 * l1 + 0.15 * grad + 0.05 * phys + 0.1 * (1.0 - ssim_mean);
    out[0] = (float)total;
    out[1] = (float)psnr;
    out[2] = (float)ssim_mean;
}

extern "C" void kernel_launch(void* const* d_in, const int* in_sizes, int n_in,
                              void* d_out, int out_size)
{
    const float* pred = (const float*)d_in[0];
    const float* targ = (const float*)d_in[1];

    // Gaussian 11-tap (sigma=1.5), normalized in double like the reference
    Wt wv;
    double g[11], s = 0.0;
    for (int i = 0; i < 11; i++) { double d = i - 5.0; g[i] = exp(-(d * d) / 4.5); s += g[i]; }
    for (int i = 0; i < 11; i++) wv.w[i] = (float)(g[i] / s);

    loss_init<<<1, 32>>>();
    dim3 grid(IMG_W / TILE_O, IMG_H / TILE_O, NB);
    loss_main<<<grid, 256>>>(pred, targ, wv);
    loss_final<<<1, 1>>>((float*)d_out);
}

// round 7
// speedup vs baseline: 1.1815x; 1.1815x over previous
#include <cuda_runtime.h>
#include <math.h>

#define IMG_H 2048
#define IMG_W 2048
#define NB 4
#define OUT_DIM 2038          // IMG - 10 (VALID 11x11)
#define TILE_O 32
#define TILE_I 42             // TILE_O + 10
#define SPITCH 45             // odd pitch -> conflict-free strided row access
#define HP2 33                // pitch: float2 units for packed arrays, floats for h1
#define GRID_X (IMG_W / TILE_O)
#define GRID_Y (IMG_H / TILE_O)
#define NBLOCKS (GRID_X * GRID_Y * NB)

typedef unsigned long long u64;

// ---------------- global accumulators (self-resetting each launch) ----------
__device__ double g_l1, g_gh, g_gw, g_range, g_ssim;
__device__ double g_sp[NB], g_st[NB], g_spp[NB], g_stt[NB];
__device__ unsigned long long g_mse[NB];
__device__ unsigned int g_done;

struct Wt { float w[11]; };

__device__ __forceinline__ u64 pack2(float lo, float hi) {
    u64 r; asm("mov.b64 %0, {%1,%2};" : "=l"(r) : "f"(lo), "f"(hi)); return r;
}
__device__ __forceinline__ void unpack2(u64 v, float& lo, float& hi) {
    asm("mov.b64 {%0,%1}, %2;" : "=f"(lo), "=f"(hi) : "l"(v));
}
__device__ __forceinline__ u64 fma2_(u64 a, u64 b, u64 c) {
    u64 d; asm("fma.rn.f32x2 %0, %1, %2, %3;" : "=l"(d) : "l"(a), "l"(b), "l"(c));
    return d;
}

__device__ __forceinline__ float quant255(float x) {
    // exact replica of reference _to_uint8_float (fp32 op-for-op)
    x = fminf(fmaxf(x, -1.0f), 1.0f);
    float x01 = fminf(fmaxf((x + 1.0f) * 0.5f, 0.0f), 1.0f);
    return floorf(fminf(fmaxf(x01 * 255.0f, 0.0f), 255.0f));
}

__global__ __launch_bounds__(256) void loss_fused(const float* __restrict__ pred,
                                                  const float* __restrict__ targ,
                                                  float* __restrict__ out,
                                                  Wt wp)
{
    __shared__ float  sP[TILE_I * SPITCH];
    __shared__ float  sT[TILE_I * SPITCH];
    __shared__ float2 h2a[TILE_I * HP2];   // (hP, hT)
    __shared__ float2 h2b[TILE_I * HP2];   // (hPP, hTT)
    __shared__ float  h1 [TILE_I * HP2];   // hPT
    __shared__ float s_redf[8][10];
    __shared__ unsigned s_redu[8];
    __shared__ bool s_last;

    const int tid = threadIdx.x;
    const int b   = blockIdx.z;
    const int by0 = blockIdx.y * TILE_O;
    const int bx0 = blockIdx.x * TILE_O;
    const size_t ioff = (size_t)b * IMG_H * IMG_W;
    const float* P = pred + ioff;
    const float* T = targ + ioff;

    float wt[11];
    u64 wt2[11];
    #pragma unroll
    for (int i = 0; i < 11; i++) { wt[i] = wp.w[i]; wt2[i] = pack2(wt[i], wt[i]); }

    // ---- Phase A: load raw tile (tile never crosses image edge: 64*32=2048,
    //      halo reads rows/cols up to by0+41; guard the bottom/right edges) ---
    for (int i = tid; i < TILE_I * TILE_I; i += 256) {
        int r = i / TILE_I, c = i - r * TILE_I;
        int gy = by0 + r, gx = bx0 + c;
        float p = 0.f, t = 0.f;
        if (gy < IMG_H && gx < IMG_W) {
            size_t gi = (size_t)gy * IMG_W + gx;
            p = P[gi];
            t = T[gi];
        }
        sP[r * SPITCH + c] = p;
        sT[r * SPITCH + c] = t;
    }
    __syncthreads();

    // ---- Phase B: per-pixel reductions over the owned 32x32 region --------
    float a_l1 = 0.f, a_gh = 0.f, a_gw = 0.f, a_rng = 0.f;
    float a_sp = 0.f, a_st = 0.f, a_spp = 0.f, a_stt = 0.f, a_ssim = 0.f;
    unsigned a_mse = 0u;
    #pragma unroll
    for (int it = 0; it < 4; it++) {
        int i = tid + it * 256;           // 0..1023
        int ly = i >> 5, lx = i & 31;
        float p = sP[ly * SPITCH + lx];
        float t = sT[ly * SPITCH + lx];
        a_l1  += fabsf(p - t);
        a_rng += fmaxf(fabsf(p) - 1.0f, 0.0f);
        a_sp  += p;  a_st  += t;
        a_spp += p * p;  a_stt += t * t;
        if (by0 + ly < IMG_H - 1) {
            a_gh += fabsf((p - sP[(ly + 1) * SPITCH + lx]) - (t - sT[(ly + 1) * SPITCH + lx]));
        }
        if (bx0 + lx < IMG_W - 1) {
            a_gw += fabsf((p - sP[ly * SPITCH + lx + 1]) - (t - sT[ly * SPITCH + lx + 1]));
        }
        float qp = quant255(p), qt = quant255(t);
        float d = qp - qt;                 // integer-valued
        a_mse += (unsigned)(d * d);        // exact (<= 65025 per px)
    }
    __syncthreads();

    // ---- Phase C: quantize tile in place ----------------------------------
    for (int i = tid; i < TILE_I * TILE_I; i += 256) {
        int r = i / TILE_I, c = i - r * TILE_I;
        int idx = r * SPITCH + c;
        sP[idx] = quant255(sP[idx]);
        sT[idx] = quant255(sT[idx]);
    }
    __syncthreads();

    // ---- Phase D: horizontal 11-tap conv, packed dual-half f32x2 ----------
    // 210 uniform branchless tasks: (field 0..4) x (row 0..41).
    // Each task computes all 32 output cols as 16 packed (lo,hi=lo+16) pairs.
    if (tid < 210) {
        int f   = tid / 42;
        int row = tid - f * 42;
        const float* ra = ((f == 1) | (f == 3)) ? (sT + row * SPITCH) : (sP + row * SPITCH);
        const float* rb = (f == 4) ? (sT + row * SPITCH) : ra;
        const bool domul = (f >= 2);

        float* dst;
        int cstride, rpitch;
        if (f < 2)      { dst = (float*)h2a + (f & 1); cstride = 2; rpitch = 2 * HP2; }
        else if (f < 4) { dst = (float*)h2b + (f & 1); cstride = 2; rpitch = 2 * HP2; }
        else            { dst = h1;                    cstride = 1; rpitch = HP2;     }
        dst += row * rpitch;

        u64 buf[11];
        #pragma unroll
        for (int j = 0; j < 10; j++) {
            float xl = ra[j],      yl = rb[j];
            float xh = ra[j + 16], yh = rb[j + 16];
            float vl = domul ? xl * yl : xl;
            float vh = domul ? xh * yh : xh;
            buf[j] = pack2(vl, vh);
        }
        #pragma unroll
        for (int oc = 0; oc < 16; oc++) {
            int c = oc + 10;
            float xl = ra[c],      yl = rb[c];
            float xh = ra[c + 16], yh = rb[c + 16];
            float vl = domul ? xl * yl : xl;
            float vh = domul ? xh * yh : xh;
            buf[(oc + 10) % 11] = pack2(vl, vh);
            u64 acc = 0ull;                       // packed (0.f, 0.f)
            #pragma unroll
            for (int k = 0; k < 11; k++) acc = fma2_(wt2[k], buf[(oc + k) % 11], acc);
            float lo, hi;
            unpack2(acc, lo, hi);
            dst[oc * cstride]        = lo;
            dst[(oc + 16) * cstride] = hi;
        }
    }
    __syncthreads();

    // ---- Phase E: vertical 11-tap conv + SSIM, all 256 threads ------------
    // thread = (col tx, row-group of 4); f32x2 windows for (m1,m2),(cpp,ctt)
    {
        const float C1F = 6.5025f;    // (0.01*255)^2
        const float C2F = 58.5225f;   // (0.03*255)^2
        const int tx    = tid & 31;
        const int rbase = (tid >> 5) * 4;   // 0,4,...,28

        u64 wa[11], wb[11];
        float wc[11];
        #pragma unroll
        for (int j = 0; j < 10; j++) {
            int rr = rbase + j;
            wa[j] = *(const u64*)&h2a[rr * HP2 + tx];
            wb[j] = *(const u64*)&h2b[rr * HP2 + tx];
            wc[j] = h1[rr * HP2 + tx];
        }
        #pragma unroll
        for (int r = 0; r < 4; r++) {
            int lr = rbase + r + 10;
            int slot = (r + 10) % 11;
            wa[slot] = *(const u64*)&h2a[lr * HP2 + tx];
            wb[slot] = *(const u64*)&h2b[lr * HP2 + tx];
            wc[slot] = h1[lr * HP2 + tx];
            u64 accA = 0ull, accB = 0ull;
            float accC = 0.f;
            #pragma unroll
            for (int k = 0; k < 11; k++) {
                int j = (r + k) % 11;
                accA = fma2_(wt2[k], wa[j], accA);
                accB = fma2_(wt2[k], wb[j], accB);
                accC = fmaf(wt[k], wc[j], accC);
            }
            if (by0 + rbase + r < OUT_DIM && bx0 + tx < OUT_DIM) {
                float m1, m2, cpp, ctt;
                unpack2(accA, m1, m2);
                unpack2(accB, cpp, ctt);
                float m1s = m1 * m1, m2s = m2 * m2, m12 = m1 * m2;
                float s1 = cpp - m1s, s2 = ctt - m2s, s12 = accC - m12;
                float num = (2.0f * m12 + C1F) * (2.0f * s12 + C2F);
                float den = (m1s + m2s + C1F) * (s1 + s2 + C2F);
                a_ssim += __fdividef(num, den);
            }
        }
    }

    // ---- Phase F: block reduction + atomics -------------------------------
    float vals[9] = {a_l1, a_gh, a_gw, a_rng, a_sp, a_st, a_spp, a_stt, a_ssim};
    #pragma unroll
    for (int q = 0; q < 9; q++) {
        float v = vals[q];
        #pragma unroll
        for (int o = 16; o > 0; o >>= 1) v += __shfl_down_sync(0xffffffffu, v, o);
        vals[q] = v;
    }
    unsigned mm = a_mse;
    #pragma unroll
    for (int o = 16; o > 0; o >>= 1) mm += __shfl_down_sync(0xffffffffu, mm, o);

    int wid = tid >> 5, lane = tid & 31;
    if (lane == 0) {
        #pragma unroll
        for (int q = 0; q < 9; q++) s_redf[wid][q] = vals[q];
        s_redu[wid] = mm;
    }
    __syncthreads();
    if (tid < 32) {
        float v[9];
        #pragma unroll
        for (int q = 0; q < 9; q++) {
            float x = (tid < 8) ? s_redf[tid][q] : 0.f;
            #pragma unroll
            for (int o = 4; o > 0; o >>= 1) x += __shfl_down_sync(0xffffffffu, x, o);
            v[q] = x;
        }
        unsigned xm = (tid < 8) ? s_redu[tid] : 0u;
        #pragma unroll
        for (int o = 4; o > 0; o >>= 1) xm += __shfl_down_sync(0xffffffffu, xm, o);
        if (tid == 0) {
            atomicAdd(&g_l1,    (double)v[0]);
            atomicAdd(&g_gh,    (double)v[1]);
            atomicAdd(&g_gw,    (double)v[2]);
            atomicAdd(&g_range, (double)v[3]);
            atomicAdd(&g_sp[b], (double)v[4]);
            atomicAdd(&g_st[b], (double)v[5]);
            atomicAdd(&g_spp[b],(double)v[6]);
            atomicAdd(&g_stt[b],(double)v[7]);
            atomicAdd(&g_ssim,  (double)v[8]);
            atomicAdd(&g_mse[b], (unsigned long long)xm);
        }
    }

    // ---- Tail: last finished block finalizes + resets for next replay -----
    if (tid == 0) {
        __threadfence();
        unsigned prev = atomicAdd(&g_done, 1u);
        s_last = (prev == (unsigned)(NBLOCKS - 1));
    }
    __syncthreads();
    if (s_last && tid == 0) {
        const double n = (double)IMG_H * (double)IMG_W;
        double l1 = g_l1 / ((double)NB * n);
        double grad = g_gh / ((double)NB * (double)(IMG_H - 1) * (double)IMG_W)
                    + g_gw / ((double)NB * (double)IMG_H * (double)(IMG_W - 1));
        double energy = 0.0, dist = 0.0, psnr = 0.0;
        for (int i = 0; i < NB; i++) {
            double pm = g_sp[i] / n, tm = g_st[i] / n;
            energy += (pm - tm) * (pm - tm);
            double ps = sqrt(fmax((g_spp[i] - n * pm * pm) / (n - 1.0), 0.0));
            double ts = sqrt(fmax((g_stt[i] - n * tm * tm) / (n - 1.0), 0.0));
            dist += (ps - ts) * (ps - ts);
            double mse = (double)g_mse[i] / n;
            psnr += (mse == 0.0) ? 100.0 : 10.0 * log10(65025.0 / mse);
        }
        energy /= NB; dist /= NB; psnr /= NB;
        double range = g_range / ((double)NB * n);
        double phys = energy + 0.5 * dist + 0.1 * range;
        double ssim_mean = g_ssim / ((double)NB * (double)OUT_DIM * (double)OUT_DIM);
        ssim_mean = fmin(fmax(ssim_mean, 0.0), 1.0);
        double total = 1.0 * l1 + 0.15 * grad + 0.05 * phys + 0.1 * (1.0 - ssim_mean);
        out[0] = (float)total;
        out[1] = (float)psnr;
        out[2] = (float)ssim_mean;

        // reset accumulators so every graph replay starts from a clean state
        g_l1 = 0.0; g_gh = 0.0; g_gw = 0.0; g_range = 0.0; g_ssim = 0.0;
        for (int i = 0; i < NB; i++) {
            g_sp[i] = 0.0; g_st[i] = 0.0; g_spp[i] = 0.0; g_stt[i] = 0.0;
            g_mse[i] = 0ull;
        }
        g_done = 0u;
        __threadfence();
    }
}

extern "C" void kernel_launch(void* const* d_in, const int* in_sizes, int n_in,
                              void* d_out, int out_size)
{
    const float* pred = (const float*)d_in[0];
    const float* targ = (const float*)d_in[1];

    // Gaussian 11-tap (sigma=1.5), normalized in double like the reference
    Wt wv;
    double g[11], s = 0.0;
    for (int i = 0; i < 11; i++) { double d = i - 5.0; g[i] = exp(-(d * d) / 4.5); s += g[i]; }
    for (int i = 0; i < 11; i++) wv.w[i] = (float)(g[i] / s);

    dim3 grid(GRID_X, GRID_Y, NB);
    loss_fused<<<grid, 256>>>(pred, targ, (float*)d_out, wv);
}

// round 8
// speedup vs baseline: 1.3839x; 1.1713x over previous
#include <cuda_runtime.h>
#include <math.h>

#define IMG_H 2048
#define IMG_W 2048
#define NB 4
#define OUT_DIM 2038          // IMG - 10 (VALID 11x11)
#define TILE_O 32
#define TILE_I 42             // TILE_O + 10
#define SPITCH 45             // odd pitch -> conflict-free strided row access
#define HP2 33                // pitch in float2 units (h2a/h2b) / floats (h1)
#define GRID_X (IMG_W / TILE_O)
#define GRID_Y (IMG_H / TILE_O)
#define NBLOCKS (GRID_X * GRID_Y * NB)

typedef unsigned long long u64;

// ---------------- global accumulators (self-resetting each launch) ----------
__device__ double g_l1, g_gh, g_gw, g_range, g_ssim;
__device__ double g_sp[NB], g_st[NB], g_spp[NB], g_stt[NB];
__device__ unsigned long long g_mse[NB];
__device__ unsigned int g_done;

struct Wt { float w[11]; };

__device__ __forceinline__ u64 pack2(float lo, float hi) {
    u64 r; asm("mov.b64 %0, {%1,%2};" : "=l"(r) : "f"(lo), "f"(hi)); return r;
}
__device__ __forceinline__ void unpack2(u64 v, float& lo, float& hi) {
    asm("mov.b64 {%0,%1}, %2;" : "=f"(lo), "=f"(hi) : "l"(v));
}
__device__ __forceinline__ u64 fma2_(u64 a, u64 b, u64 c) {
    u64 d; asm("fma.rn.f32x2 %0, %1, %2, %3;" : "=l"(d) : "l"(a), "l"(b), "l"(c));
    return d;
}
__device__ __forceinline__ u64 mul2_(u64 a, u64 b) {
    u64 d; asm("mul.rn.f32x2 %0, %1, %2;" : "=l"(d) : "l"(a), "l"(b));
    return d;
}

__device__ __forceinline__ float quant255(float x) {
    // exact replica of reference _to_uint8_float (fp32 op-for-op)
    x = fminf(fmaxf(x, -1.0f), 1.0f);
    float x01 = fminf(fmaxf((x + 1.0f) * 0.5f, 0.0f), 1.0f);
    return floorf(fminf(fmaxf(x01 * 255.0f, 0.0f), 255.0f));
}

// symmetric tap index: w[k] == w[10-k]
#define KSYM(k) ((k) < 6 ? (k) : 10 - (k))

__global__ __launch_bounds__(256, 4) void loss_fused(const float* __restrict__ pred,
                                                     const float* __restrict__ targ,
                                                     float* __restrict__ out,
                                                     Wt wp)
{
    __shared__ float  sP[TILE_I * SPITCH];
    __shared__ float  sT[TILE_I * SPITCH];
    __shared__ float2 h2a[TILE_I * HP2];   // (hP, hT)
    __shared__ float2 h2b[TILE_I * HP2];   // (hPP, hTT)
    __shared__ float  h1 [TILE_I * HP2];   // hPT
    __shared__ float s_redf[8][10];
    __shared__ unsigned s_redu[8];
    __shared__ bool s_last;

    const int tid = threadIdx.x;
    const int b   = blockIdx.z;
    const int by0 = blockIdx.y * TILE_O;
    const int bx0 = blockIdx.x * TILE_O;
    const size_t ioff = (size_t)b * IMG_H * IMG_W;
    const float* P = pred + ioff;
    const float* T = targ + ioff;

    // 6 distinct Gaussian taps (w[k] = w[10-k])
    float wf[6];
    u64 w2[6];
    #pragma unroll
    for (int i = 0; i < 6; i++) { wf[i] = wp.w[i]; w2[i] = pack2(wf[i], wf[i]); }

    // ---- Phase A: load raw tile (guard bottom/right image edge) -----------
    for (int i = tid; i < TILE_I * TILE_I; i += 256) {
        int r = i / TILE_I, c = i - r * TILE_I;
        int gy = by0 + r, gx = bx0 + c;
        float p = 0.f, t = 0.f;
        if (gy < IMG_H && gx < IMG_W) {
            size_t gi = (size_t)gy * IMG_W + gx;
            p = P[gi];
            t = T[gi];
        }
        sP[r * SPITCH + c] = p;
        sT[r * SPITCH + c] = t;
    }
    __syncthreads();

    // ---- Phase B: per-pixel reductions over the owned 32x32 region --------
    float a_l1 = 0.f, a_gh = 0.f, a_gw = 0.f, a_rng = 0.f;
    float a_sp = 0.f, a_st = 0.f, a_spp = 0.f, a_stt = 0.f, a_ssim = 0.f;
    unsigned a_mse = 0u;
    #pragma unroll
    for (int it = 0; it < 4; it++) {
        int i = tid + it * 256;           // 0..1023
        int ly = i >> 5, lx = i & 31;
        float p = sP[ly * SPITCH + lx];
        float t = sT[ly * SPITCH + lx];
        a_l1  += fabsf(p - t);
        a_rng += fmaxf(fabsf(p) - 1.0f, 0.0f);
        a_sp  += p;  a_st  += t;
        a_spp += p * p;  a_stt += t * t;
        if (by0 + ly < IMG_H - 1) {
            a_gh += fabsf((p - sP[(ly + 1) * SPITCH + lx]) - (t - sT[(ly + 1) * SPITCH + lx]));
        }
        if (bx0 + lx < IMG_W - 1) {
            a_gw += fabsf((p - sP[ly * SPITCH + lx + 1]) - (t - sT[ly * SPITCH + lx + 1]));
        }
        float qp = quant255(p), qt = quant255(t);
        float d = qp - qt;                 // integer-valued
        a_mse += (unsigned)(d * d);        // exact (<= 65025 per px)
    }
    __syncthreads();

    // ---- Phase C: quantize tile in place ----------------------------------
    for (int i = tid; i < TILE_I * TILE_I; i += 256) {
        int r = i / TILE_I, c = i - r * TILE_I;
        int idx = r * SPITCH + c;
        sP[idx] = quant255(sP[idx]);
        sT[idx] = quant255(sT[idx]);
    }
    __syncthreads();

    // ---- Phase D: horizontal 11-tap conv, shared-source half-row tasks ----
    // 252 tasks: group g (0: P -> hP+hPP, 1: T -> hT+hTT, 2: P*T -> hPT)
    //            x 42 rows x 2 column-halves (16 outputs each, dual-packed +8)
    if (tid < 252) {
        int g    = tid / 84;
        int u    = tid - g * 84;
        int row  = u % 42;
        int half = u / 42;                 // 0: cols 0-15, 1: cols 16-31
        int c0   = half * 16;

        if (g < 2) {
            const float* r0 = (g ? sT : sP) + row * SPITCH + c0;
            u64 acc1[8], acc2[8];
            #pragma unroll
            for (int o = 0; o < 8; o++) { acc1[o] = 0ull; acc2[o] = 0ull; }
            #pragma unroll
            for (int j = 0; j < 18; j++) {
                u64 v  = pack2(r0[j], r0[j + 8]);
                u64 vs = mul2_(v, v);
                #pragma unroll
                for (int o = 0; o < 8; o++) {
                    int k = j - o;
                    if (k >= 0 && k < 11) {
                        acc1[o] = fma2_(w2[KSYM(k)], v,  acc1[o]);
                        acc2[o] = fma2_(w2[KSYM(k)], vs, acc2[o]);
                    }
                }
            }
            float* d1 = (float*)h2a + row * (2 * HP2) + g;
            float* d2 = (float*)h2b + row * (2 * HP2) + g;
            #pragma unroll
            for (int o = 0; o < 8; o++) {
                float lo, hi;
                unpack2(acc1[o], lo, hi);
                d1[(c0 + o) * 2]     = lo;
                d1[(c0 + o + 8) * 2] = hi;
                unpack2(acc2[o], lo, hi);
                d2[(c0 + o) * 2]     = lo;
                d2[(c0 + o + 8) * 2] = hi;
            }
        } else {
            const float* rp = sP + row * SPITCH + c0;
            const float* rt = sT + row * SPITCH + c0;
            u64 acc[8];
            #pragma unroll
            for (int o = 0; o < 8; o++) acc[o] = 0ull;
            #pragma unroll
            for (int j = 0; j < 18; j++) {
                u64 v = mul2_(pack2(rp[j], rp[j + 8]), pack2(rt[j], rt[j + 8]));
                #pragma unroll
                for (int o = 0; o < 8; o++) {
                    int k = j - o;
                    if (k >= 0 && k < 11) acc[o] = fma2_(w2[KSYM(k)], v, acc[o]);
                }
            }
            float* d = h1 + row * HP2;
            #pragma unroll
            for (int o = 0; o < 8; o++) {
                float lo, hi;
                unpack2(acc[o], lo, hi);
                d[c0 + o]     = lo;
                d[c0 + o + 8] = hi;
            }
        }
    }
    __syncthreads();

    // ---- Phase E: vertical 11-tap conv + SSIM (scatter form, 256 threads) -
    {
        const float C1F = 6.5025f;    // (0.01*255)^2
        const float C2F = 58.5225f;   // (0.03*255)^2
        const int tx    = tid & 31;
        const int rbase = (tid >> 5) * 4;   // 0,4,...,28

        u64 accA[4], accB[4];
        float accC[4];
        #pragma unroll
        for (int r = 0; r < 4; r++) { accA[r] = 0ull; accB[r] = 0ull; accC[r] = 0.f; }

        #pragma unroll
        for (int j = 0; j < 14; j++) {
            int rr = rbase + j;
            u64 va   = *(const u64*)&h2a[rr * HP2 + tx];
            u64 vb   = *(const u64*)&h2b[rr * HP2 + tx];
            float vc = h1[rr * HP2 + tx];
            #pragma unroll
            for (int r = 0; r < 4; r++) {
                int k = j - r;
                if (k >= 0 && k < 11) {
                    accA[r] = fma2_(w2[KSYM(k)], va, accA[r]);
                    accB[r] = fma2_(w2[KSYM(k)], vb, accB[r]);
                    accC[r] = fmaf(wf[KSYM(k)], vc, accC[r]);
                }
            }
        }
        #pragma unroll
        for (int r = 0; r < 4; r++) {
            if (by0 + rbase + r < OUT_DIM && bx0 + tx < OUT_DIM) {
                float m1, m2, cpp, ctt;
                unpack2(accA[r], m1, m2);
                unpack2(accB[r], cpp, ctt);
                float m1s = m1 * m1, m2s = m2 * m2, m12 = m1 * m2;
                float s1 = cpp - m1s, s2 = ctt - m2s, s12 = accC[r] - m12;
                float num = (2.0f * m12 + C1F) * (2.0f * s12 + C2F);
                float den = (m1s + m2s + C1F) * (s1 + s2 + C2F);
                a_ssim += __fdividef(num, den);
            }
        }
    }

    // ---- Phase F: block reduction + atomics -------------------------------
    float vals[9] = {a_l1, a_gh, a_gw, a_rng, a_sp, a_st, a_spp, a_stt, a_ssim};
    #pragma unroll
    for (int q = 0; q < 9; q++) {
        float v = vals[q];
        #pragma unroll
        for (int o = 16; o > 0; o >>= 1) v += __shfl_down_sync(0xffffffffu, v, o);
        vals[q] = v;
    }
    unsigned mm = a_mse;
    #pragma unroll
    for (int o = 16; o > 0; o >>= 1) mm += __shfl_down_sync(0xffffffffu, mm, o);

    int wid = tid >> 5, lane = tid & 31;
    if (lane == 0) {
        #pragma unroll
        for (int q = 0; q < 9; q++) s_redf[wid][q] = vals[q];
        s_redu[wid] = mm;
    }
    __syncthreads();
    if (tid < 32) {
        float v[9];
        #pragma unroll
        for (int q = 0; q < 9; q++) {
            float x = (tid < 8) ? s_redf[tid][q] : 0.f;
            #pragma unroll
            for (int o = 4; o > 0; o >>= 1) x += __shfl_down_sync(0xffffffffu, x, o);
            v[q] = x;
        }
        unsigned xm = (tid < 8) ? s_redu[tid] : 0u;
        #pragma unroll
        for (int o = 4; o > 0; o >>= 1) xm += __shfl_down_sync(0xffffffffu, xm, o);
        if (tid == 0) {
            atomicAdd(&g_l1,    (double)v[0]);
            atomicAdd(&g_gh,    (double)v[1]);
            atomicAdd(&g_gw,    (double)v[2]);
            atomicAdd(&g_range, (double)v[3]);
            atomicAdd(&g_sp[b], (double)v[4]);
            atomicAdd(&g_st[b], (double)v[5]);
            atomicAdd(&g_spp[b],(double)v[6]);
            atomicAdd(&g_stt[b],(double)v[7]);
            atomicAdd(&g_ssim,  (double)v[8]);
            atomicAdd(&g_mse[b], (unsigned long long)xm);
        }
    }

    // ---- Tail: last finished block finalizes + resets for next replay -----
    if (tid == 0) {
        __threadfence();
        unsigned prev = atomicAdd(&g_done, 1u);
        s_last = (prev == (unsigned)(NBLOCKS - 1));
    }
    __syncthreads();
    if (s_last && tid == 0) {
        const double n = (double)IMG_H * (double)IMG_W;
        double l1 = g_l1 / ((double)NB * n);
        double grad = g_gh / ((double)NB * (double)(IMG_H - 1) * (double)IMG_W)
                    + g_gw / ((double)NB * (double)IMG_H * (double)(IMG_W - 1));
        double energy = 0.0, dist = 0.0, psnr = 0.0;
        for (int i = 0; i < NB; i++) {
            double pm = g_sp[i] / n, tm = g_st[i] / n;
            energy += (pm - tm) * (pm - tm);
            double ps = sqrt(fmax((g_spp[i] - n * pm * pm) / (n - 1.0), 0.0));
            double ts = sqrt(fmax((g_stt[i] - n * tm * tm) / (n - 1.0), 0.0));
            dist += (ps - ts) * (ps - ts);
            double mse = (double)g_mse[i] / n;
            psnr += (mse == 0.0) ? 100.0 : 10.0 * log10(65025.0 / mse);
        }
        energy /= NB; dist /= NB; psnr /= NB;
        double range = g_range / ((double)NB * n);
        double phys = energy + 0.5 * dist + 0.1 * range;
        double ssim_mean = g_ssim / ((double)NB * (double)OUT_DIM * (double)OUT_DIM);
        ssim_mean = fmin(fmax(ssim_mean, 0.0), 1.0);
        double total = 1.0 * l1 + 0.15 * grad + 0.05 * phys + 0.1 * (1.0 - ssim_mean);
        out[0] = (float)total;
        out[1] = (float)psnr;
        out[2] = (float)ssim_mean;

        // reset accumulators so every graph replay starts from a clean state
        g_l1 = 0.0; g_gh = 0.0; g_gw = 0.0; g_range = 0.0; g_ssim = 0.0;
        for (int i = 0; i < NB; i++) {
            g_sp[i] = 0.0; g_st[i] = 0.0; g_spp[i] = 0.0; g_stt[i] = 0.0;
            g_mse[i] = 0ull;
        }
        g_done = 0u;
        __threadfence();
    }
}

extern "C" void kernel_launch(void* const* d_in, const int* in_sizes, int n_in,
                              void* d_out, int out_size)
{
    const float* pred = (const float*)d_in[0];
    const float* targ = (const float*)d_in[1];

    // Gaussian 11-tap (sigma=1.5), normalized in double like the reference
    Wt wv;
    double g[11], s = 0.0;
    for (int i = 0; i < 11; i++) { double d = i - 5.0; g[i] = exp(-(d * d) / 4.5); s += g[i]; }
    for (int i = 0; i < 11; i++) wv.w[i] = (float)(g[i] / s);

    dim3 grid(GRID_X, GRID_Y, NB);
    loss_fused<<<grid, 256>>>(pred, targ, (float*)d_out, wv);
}

// round 10
// speedup vs baseline: 1.7867x; 1.2911x over previous
#include <cuda_runtime.h>
#include <math.h>

#define IMG_H 2048
#define IMG_W 2048
#define NB 4
#define OUT_DIM 2038          // IMG - 10 (VALID 11x11)
#define TILE_O 32
#define TILE_I 42             // TILE_O + 10
#define SPITCH 45             // odd pitch -> conflict-free strided row access
#define HP2 33                // pitch in float2 units (h2a/h2b) / floats (h1)
#define GRID_X (IMG_W / TILE_O)
#define GRID_Y (IMG_H / TILE_O)
#define NBLOCKS (GRID_X * GRID_Y * NB)
#define HALO_N (TILE_I * TILE_I - TILE_O * TILE_O)   // 740

typedef unsigned long long u64;

// ---------------- global accumulators (self-resetting each launch) ----------
__device__ double g_l1, g_gh, g_gw, g_range, g_ssim;
__device__ double g_sp[NB], g_st[NB], g_spp[NB], g_stt[NB];
__device__ unsigned long long g_mse[NB];
__device__ unsigned int g_done;

struct Wt { float w[11]; };

__device__ __forceinline__ u64 pack2(float lo, float hi) {
    u64 r; asm("mov.b64 %0, {%1,%2};" : "=l"(r) : "f"(lo), "f"(hi)); return r;
}
__device__ __forceinline__ void unpack2(u64 v, float& lo, float& hi) {
    asm("mov.b64 {%0,%1}, %2;" : "=f"(lo), "=f"(hi) : "l"(v));
}
__device__ __forceinline__ u64 fma2_(u64 a, u64 b, u64 c) {
    u64 d; asm("fma.rn.f32x2 %0, %1, %2, %3;" : "=l"(d) : "l"(a), "l"(b), "l"(c));
    return d;
}
__device__ __forceinline__ u64 mul2_(u64 a, u64 b) {
    u64 d; asm("mul.rn.f32x2 %0, %1, %2;" : "=l"(d) : "l"(a), "l"(b));
    return d;
}

__device__ __forceinline__ float quant255(float x) {
    // exact replica of reference _to_uint8_float (fp32 op-for-op)
    x = fminf(fmaxf(x, -1.0f), 1.0f);
    float x01 = fminf(fmaxf((x + 1.0f) * 0.5f, 0.0f), 1.0f);
    return floorf(fminf(fmaxf(x01 * 255.0f, 0.0f), 255.0f));
}

// symmetric tap index: w[k] == w[10-k]
#define KSYM(k) ((k) < 6 ? (k) : 10 - (k))

__global__ __launch_bounds__(256, 4) void loss_fused(const float* __restrict__ pred,
                                                     const float* __restrict__ targ,
                                                     float* __restrict__ out,
                                                     Wt wp)
{
    __shared__ float  sP[TILE_I * SPITCH];   // QUANTIZED tile
    __shared__ float  sT[TILE_I * SPITCH];
    __shared__ float2 h2a[TILE_I * HP2];     // (hP, hT)
    __shared__ float2 h2b[TILE_I * HP2];     // (hPP, hTT)
    __shared__ float  h1 [TILE_I * HP2];     // hPT
    __shared__ float s_redf[8][10];
    __shared__ unsigned s_redu[8];
    __shared__ bool s_last;

    const int tid = threadIdx.x;
    const int b   = blockIdx.z;
    const int by0 = blockIdx.y * TILE_O;
    const int bx0 = blockIdx.x * TILE_O;
    const size_t ioff = (size_t)b * IMG_H * IMG_W;
    const float* P = pred + ioff;
    const float* T = targ + ioff;

    // 6 distinct Gaussian taps (w[k] = w[10-k])
    float wf[6];
    u64 w2[6];
    #pragma unroll
    for (int i = 0; i < 6; i++) { wf[i] = wp.w[i]; w2[i] = pack2(wf[i], wf[i]); }

    float a_l1 = 0.f, a_gh = 0.f, a_gw = 0.f, a_rng = 0.f;
    float a_sp = 0.f, a_st = 0.f, a_spp = 0.f, a_stt = 0.f, a_ssim = 0.f;
    unsigned a_mse = 0u;

    // ---- Phase A (fused): owned 32x32 -> stats in registers + quantized store
    {
        const int ly  = tid >> 3;             // 0..31
        const int lxq = (tid & 7) * 4;        // 0,4,...,28
        const int gy = by0 + ly, gx = bx0 + lxq;
        const float* prow = P + (size_t)gy * IMG_W + gx;
        const float* trow = T + (size_t)gy * IMG_W + gx;
        float4 p4 = *(const float4*)prow;
        float4 t4 = *(const float4*)trow;
        const bool down_ok = (gy + 1) < IMG_H;
        float4 pd4 = down_ok ? *(const float4*)(prow + IMG_W) : p4;
        float4 td4 = down_ok ? *(const float4*)(trow + IMG_W) : t4;

        // right neighbor of the quad: next lane's first element (quad edge:
        // scalar load; at image edge the gw term is skipped anyway)
        float pn = __shfl_down_sync(0xffffffffu, p4.x, 1);
        float tn = __shfl_down_sync(0xffffffffu, t4.x, 1);
        if ((tid & 7) == 7) {
            const bool rok = (gx + 4) < IMG_W;
            pn = rok ? prow[4] : 0.f;
            tn = rok ? trow[4] : 0.f;
        }
        float pv[5] = {p4.x, p4.y, p4.z, p4.w, pn};
        float tv[5] = {t4.x, t4.y, t4.z, t4.w, tn};
        float pd[4] = {pd4.x, pd4.y, pd4.z, pd4.w};
        float td[4] = {td4.x, td4.y, td4.z, td4.w};

        #pragma unroll
        for (int c = 0; c < 4; c++) {
            float p = pv[c], t = tv[c];
            a_l1  += fabsf(p - t);
            a_rng += fmaxf(fabsf(p) - 1.0f, 0.0f);
            a_sp  += p;  a_st  += t;
            a_spp += p * p;  a_stt += t * t;
            if (down_ok)            a_gh += fabsf((p - pd[c]) - (t - td[c]));
            if (gx + c < IMG_W - 1) a_gw += fabsf((p - pv[c + 1]) - (t - tv[c + 1]));
            float qp = quant255(p), qt = quant255(t);
            float d = qp - qt;                 // integer-valued
            a_mse += (unsigned)(d * d);        // exact (<= 65025 per px)
            sP[ly * SPITCH + lxq + c] = qp;
            sT[ly * SPITCH + lxq + c] = qt;
        }
    }

    // ---- halo ring: quantize-on-store (OOB -> quant(0); feeds only invalid outputs)
    for (int i = tid; i < HALO_N; i += 256) {
        int r, c;
        if (i < 420) { r = 32 + i / 42; c = i - (i / 42) * 42; }
        else         { int j = i - 420; r = j / 10; c = 32 + (j - (j / 10) * 10); }
        int gy = by0 + r, gx = bx0 + c;
        float p = 0.f, t = 0.f;
        if (gy < IMG_H && gx < IMG_W) {
            size_t gi = (size_t)gy * IMG_W + gx;
            p = P[gi];
            t = T[gi];
        }
        sP[r * SPITCH + c] = quant255(p);
        sT[r * SPITCH + c] = quant255(t);
    }
    __syncthreads();

    // ---- Phase D: horizontal 11-tap conv, shared-source half-row tasks ----
    // 252 tasks: group g (0: P -> hP+hPP, 1: T -> hT+hTT, 2: P*T -> hPT)
    //            x 42 rows x 2 column-halves (16 outputs each, dual-packed +8)
    if (tid < 252) {
        int g    = tid / 84;
        int u    = tid - g * 84;
        int row  = u % 42;
        int half = u / 42;                 // 0: cols 0-15, 1: cols 16-31
        int c0   = half * 16;

        if (g < 2) {
            const float* r0 = (g ? sT : sP) + row * SPITCH + c0;
            u64 acc1[8], acc2[8];
            #pragma unroll
            for (int o = 0; o < 8; o++) { acc1[o] = 0ull; acc2[o] = 0ull; }
            #pragma unroll
            for (int j = 0; j < 18; j++) {
                u64 v  = pack2(r0[j], r0[j + 8]);
                u64 vs = mul2_(v, v);
                #pragma unroll
                for (int o = 0; o < 8; o++) {
                    int k = j - o;
                    if (k >= 0 && k < 11) {
                        acc1[o] = fma2_(w2[KSYM(k)], v,  acc1[o]);
                        acc2[o] = fma2_(w2[KSYM(k)], vs, acc2[o]);
                    }
                }
            }
            float* d1 = (float*)h2a + row * (2 * HP2) + g;
            float* d2 = (float*)h2b + row * (2 * HP2) + g;
            #pragma unroll
            for (int o = 0; o < 8; o++) {
                float lo, hi;
                unpack2(acc1[o], lo, hi);
                d1[(c0 + o) * 2]     = lo;
                d1[(c0 + o + 8) * 2] = hi;
                unpack2(acc2[o], lo, hi);
                d2[(c0 + o) * 2]     = lo;
                d2[(c0 + o + 8) * 2] = hi;
            }
        } else {
            const float* rp = sP + row * SPITCH + c0;
            const float* rt = sT + row * SPITCH + c0;
            u64 acc[8];
            #pragma unroll
            for (int o = 0; o < 8; o++) acc[o] = 0ull;
            #pragma unroll
            for (int j = 0; j < 18; j++) {
                u64 v = mul2_(pack2(rp[j], rp[j + 8]), pack2(rt[j], rt[j + 8]));
                #pragma unroll
                for (int o = 0; o < 8; o++) {
                    int k = j - o;
                    if (k >= 0 && k < 11) acc[o] = fma2_(w2[KSYM(k)], v, acc[o]);
                }
            }
            float* d = h1 + row * HP2;
            #pragma unroll
            for (int o = 0; o < 8; o++) {
                float lo, hi;
                unpack2(acc[o], lo, hi);
                d[c0 + o]     = lo;
                d[c0 + o + 8] = hi;
            }
        }
    }
    __syncthreads();

    // ---- Phase E: vertical 11-tap conv + SSIM (scatter form, 256 threads) -
    {
        const float C1F = 6.5025f;    // (0.01*255)^2
        const float C2F = 58.5225f;   // (0.03*255)^2
        const int tx    = tid & 31;
        const int rbase = (tid >> 5) * 4;   // 0,4,...,28

        u64 accA[4], accB[4];
        float accC[4];
        #pragma unroll
        for (int r = 0; r < 4; r++) { accA[r] = 0ull; accB[r] = 0ull; accC[r] = 0.f; }

        #pragma unroll
        for (int j = 0; j < 14; j++) {
            int rr = rbase + j;
            u64 va   = *(const u64*)&h2a[rr * HP2 + tx];
            u64 vb   = *(const u64*)&h2b[rr * HP2 + tx];
            float vc = h1[rr * HP2 + tx];
            #pragma unroll
            for (int r = 0; r < 4; r++) {
                int k = j - r;
                if (k >= 0 && k < 11) {
                    accA[r] = fma2_(w2[KSYM(k)], va, accA[r]);
                    accB[r] = fma2_(w2[KSYM(k)], vb, accB[r]);
                    accC[r] = fmaf(wf[KSYM(k)], vc, accC[r]);
                }
            }
        }
        const bool xok = (bx0 + tx) < OUT_DIM;
        #pragma unroll
        for (int r = 0; r < 4; r++) {
            if (xok && (by0 + rbase + r) < OUT_DIM) {
                float m1, m2, cpp, ctt;
                unpack2(accA[r], m1, m2);
                unpack2(accB[r], cpp, ctt);
                float m1s = m1 * m1, m2s = m2 * m2, m12 = m1 * m2;
                float s1 = cpp - m1s, s2 = ctt - m2s, s12 = accC[r] - m12;
                float num = (2.0f * m12 + C1F) * (2.0f * s12 + C2F);
                float den = (m1s + m2s + C1F) * (s1 + s2 + C2F);
                a_ssim += __fdividef(num, den);
            }
        }
    }

    // ---- Phase F: block reduction + atomics -------------------------------
    float vals[9] = {a_l1, a_gh, a_gw, a_rng, a_sp, a_st, a_spp, a_stt, a_ssim};
    #pragma unroll
    for (int q = 0; q < 9; q++) {
        float v = vals[q];
        #pragma unroll
        for (int o = 16; o > 0; o >>= 1) v += __shfl_down_sync(0xffffffffu, v, o);
        vals[q] = v;
    }
    unsigned mm = a_mse;
    #pragma unroll
    for (int o = 16; o > 0; o >>= 1) mm += __shfl_down_sync(0xffffffffu, mm, o);

    int wid = tid >> 5, lane = tid & 31;
    if (lane == 0) {
        #pragma unroll
        for (int q = 0; q < 9; q++) s_redf[wid][q] = vals[q];
        s_redu[wid] = mm;
    }
    __syncthreads();
    if (tid < 32) {
        float v[9];
        #pragma unroll
        for (int q = 0; q < 9; q++) {
            float x = (tid < 8) ? s_redf[tid][q] : 0.f;
            #pragma unroll
            for (int o = 4; o > 0; o >>= 1) x += __shfl_down_sync(0xffffffffu, x, o);
            v[q] = x;
        }
        unsigned xm = (tid < 8) ? s_redu[tid] : 0u;
        #pragma unroll
        for (int o = 4; o > 0; o >>= 1) xm += __shfl_down_sync(0xffffffffu, xm, o);
        if (tid == 0) {
            atomicAdd(&g_l1,    (double)v[0]);
            atomicAdd(&g_gh,    (double)v[1]);
            atomicAdd(&g_gw,    (double)v[2]);
            atomicAdd(&g_range, (double)v[3]);
            atomicAdd(&g_sp[b], (double)v[4]);
            atomicAdd(&g_st[b], (double)v[5]);
            atomicAdd(&g_spp[b],(double)v[6]);
            atomicAdd(&g_stt[b],(double)v[7]);
            atomicAdd(&g_ssim,  (double)v[8]);
            atomicAdd(&g_mse[b], (unsigned long long)xm);
        }
    }

    // ---- Tail: last finished block finalizes + resets for next replay -----
    if (tid == 0) {
        __threadfence();
        unsigned prev = atomicAdd(&g_done, 1u);
        s_last = (prev == (unsigned)(NBLOCKS - 1));
    }
    __syncthreads();
    if (s_last && tid == 0) {
        const double n = (double)IMG_H * (double)IMG_W;
        double l1 = g_l1 / ((double)NB * n);
        double grad = g_gh / ((double)NB * (double)(IMG_H - 1) * (double)IMG_W)
                    + g_gw / ((double)NB * (double)IMG_H * (double)(IMG_W - 1));
        double energy = 0.0, dist = 0.0, psnr = 0.0;
        for (int i = 0; i < NB; i++) {
            double pm = g_sp[i] / n, tm = g_st[i] / n;
            energy += (pm - tm) * (pm - tm);
            double ps = sqrt(fmax((g_spp[i] - n * pm * pm) / (n - 1.0), 0.0));
            double ts = sqrt(fmax((g_stt[i] - n * tm * tm) / (n - 1.0), 0.0));
            dist += (ps - ts) * (ps - ts);
            double mse = (double)g_mse[i] / n;
            psnr += (mse == 0.0) ? 100.0 : 10.0 * log10(65025.0 / mse);
        }
        energy /= NB; dist /= NB; psnr /= NB;
        double range = g_range / ((double)NB * n);
        double phys = energy + 0.5 * dist + 0.1 * range;
        double ssim_mean = g_ssim / ((double)NB * (double)OUT_DIM * (double)OUT_DIM);
        ssim_mean = fmin(fmax(ssim_mean, 0.0), 1.0);
        double total = 1.0 * l1 + 0.15 * grad + 0.05 * phys + 0.1 * (1.0 - ssim_mean);
        out[0] = (float)total;
        out[1] = (float)psnr;
        out[2] = (float)ssim_mean;

        // reset accumulators so every graph replay starts from a clean state
        g_l1 = 0.0; g_gh = 0.0; g_gw = 0.0; g_range = 0.0; g_ssim = 0.0;
        for (int i = 0; i < NB; i++) {
            g_sp[i] = 0.0; g_st[i] = 0.0; g_spp[i] = 0.0; g_stt[i] = 0.0;
            g_mse[i] = 0ull;
        }
        g_done = 0u;
        __threadfence();
    }
}

extern "C" void kernel_launch(void* const* d_in, const int* in_sizes, int n_in,
                              void* d_out, int out_size)
{
    const float* pred = (const float*)d_in[0];
    const float* targ = (const float*)d_in[1];

    // Gaussian 11-tap (sigma=1.5), normalized in double like the reference
    Wt wv;
    double g[11], s = 0.0;
    for (int i = 0; i < 11; i++) { double d = i - 5.0; g[i] = exp(-(d * d) / 4.5); s += g[i]; }
    for (int i = 0; i < 11; i++) wv.w[i] = (float)(g[i] / s);

    dim3 grid(GRID_X, GRID_Y, NB);
    loss_fused<<<grid, 256>>>(pred, targ, (float*)d_out, wv);
}

// round 13
// speedup vs baseline: 1.9668x; 1.1008x over previous
#include <cuda_runtime.h>
#include <math.h>

#define IMG_H 2048
#define IMG_W 2048
#define NB 4
#define OUT_DIM 2038          // IMG - 10 (VALID 11x11)
#define TILE_O 32
#define TILE_I 42             // TILE_O + 10
#define SPITCH 45             // odd pitch -> conflict-free strided row access
#define HP2 33                // pitch in float2 units (h2a/h2b) / floats (h1)
#define GRID_X (IMG_W / TILE_O)
#define GRID_Y (IMG_H / TILE_O)
#define NBLOCKS (GRID_X * GRID_Y * NB)
#define HALO_N (TILE_I * TILE_I - TILE_O * TILE_O)   // 740

typedef unsigned long long u64;

// ---------------- global accumulators (self-resetting each launch) ----------
__device__ double g_l1, g_gh, g_gw, g_range, g_ssim;
__device__ double g_sp[NB], g_st[NB], g_spp[NB], g_stt[NB];
__device__ unsigned long long g_mse[NB];
__device__ unsigned int g_done;

struct Wt { float w[11]; };

__device__ __forceinline__ u64 pack2(float lo, float hi) {
    u64 r; asm("mov.b64 %0, {%1,%2};" : "=l"(r) : "f"(lo), "f"(hi)); return r;
}
__device__ __forceinline__ void unpack2(u64 v, float& lo, float& hi) {
    asm("mov.b64 {%0,%1}, %2;" : "=f"(lo), "=f"(hi) : "l"(v));
}
__device__ __forceinline__ u64 fma2_(u64 a, u64 b, u64 c) {
    u64 d; asm("fma.rn.f32x2 %0, %1, %2, %3;" : "=l"(d) : "l"(a), "l"(b), "l"(c));
    return d;
}

// Fast quant: reference is floor(clip(clip((clip(x,-1,1)+1)*0.5,0,1)*255,0,255)).
// For clipped x, (x+1)*0.5 in [0,1] and *255 in [0,255] exactly, so the outer
// clips are redundant; fusing *0.5*255+127.5 into one fma differs by <=2 ulp
// (can flip ~1e-5 of pixels by +-1 quantum -> ~1e-7 on PSNR/SSIM, way inside tol).
__device__ __forceinline__ float quant255(float x) {
    x = fminf(fmaxf(x, -1.0f), 1.0f);
    return floorf(fmaf(x, 127.5f, 127.5f));
}

// symmetric tap index: w[k] == w[10-k]
#define KSYM(k) ((k) < 6 ? (k) : 10 - (k))

__global__ __launch_bounds__(256, 4) void loss_fused(const float* __restrict__ pred,
                                                     const float* __restrict__ targ,
                                                     float* __restrict__ out,
                                                     Wt wp)
{
    __shared__ float  sP[TILE_I * SPITCH];   // QUANTIZED tile
    __shared__ float  sT[TILE_I * SPITCH];
    __shared__ float2 h2a[TILE_I * HP2 + 1]; // (hP,  hPP) pairs
    __shared__ float2 h2b[TILE_I * HP2 + 1]; // (hT,  hTT) pairs
    __shared__ float  h1 [TILE_I * HP2];     // hPT
    __shared__ float s_redf[8][10];
    __shared__ unsigned s_redu[8];
    __shared__ bool s_last;

    const int tid = threadIdx.x;
    const int b   = blockIdx.z;
    const int by0 = blockIdx.y * TILE_O;
    const int bx0 = blockIdx.x * TILE_O;
    const size_t ioff = (size_t)b * IMG_H * IMG_W;
    const float* P = pred + ioff;
    const float* T = targ + ioff;

    // 6 distinct Gaussian taps (w[k] = w[10-k])
    float wf[6];
    u64 w2[6];
    #pragma unroll
    for (int i = 0; i < 6; i++) { wf[i] = wp.w[i]; w2[i] = pack2(wf[i], wf[i]); }

    float a_l1 = 0.f, a_gh = 0.f, a_gw = 0.f, a_rng = 0.f;
    float a_sp = 0.f, a_st = 0.f, a_spp = 0.f, a_stt = 0.f, a_ssim = 0.f;
    unsigned a_mse = 0u;

    // ---- Phase A (fused): owned 32x32 -> stats in registers + quantized store
    {
        const int ly  = tid >> 3;             // 0..31
        const int lxq = (tid & 7) * 4;        // 0,4,...,28
        const int gy = by0 + ly, gx = bx0 + lxq;
        const float* prow = P + (size_t)gy * IMG_W + gx;
        const float* trow = T + (size_t)gy * IMG_W + gx;
        float4 p4 = *(const float4*)prow;
        float4 t4 = *(const float4*)trow;
        const bool down_ok = (gy + 1) < IMG_H;
        float4 pd4 = down_ok ? *(const float4*)(prow + IMG_W) : p4;
        float4 td4 = down_ok ? *(const float4*)(trow + IMG_W) : t4;

        // right neighbor of the quad: next lane's first element (quad edge:
        // scalar load; at image edge the gw term is skipped anyway)
        float pn = __shfl_down_sync(0xffffffffu, p4.x, 1);
        float tn = __shfl_down_sync(0xffffffffu, t4.x, 1);
        if ((tid & 7) == 7) {
            const bool rok = (gx + 4) < IMG_W;
            pn = rok ? prow[4] : 0.f;
            tn = rok ? trow[4] : 0.f;
        }
        float pv[5] = {p4.x, p4.y, p4.z, p4.w, pn};
        float tv[5] = {t4.x, t4.y, t4.z, t4.w, tn};
        float pd[4] = {pd4.x, pd4.y, pd4.z, pd4.w};
        float td[4] = {td4.x, td4.y, td4.z, td4.w};

        #pragma unroll
        for (int c = 0; c < 4; c++) {
            float p = pv[c], t = tv[c];
            a_l1  += fabsf(p - t);
            a_rng += fmaxf(fabsf(p) - 1.0f, 0.0f);
            a_sp  += p;  a_st  += t;
            a_spp += p * p;  a_stt += t * t;
            if (down_ok)            a_gh += fabsf((p - pd[c]) - (t - td[c]));
            if (gx + c < IMG_W - 1) a_gw += fabsf((p - pv[c + 1]) - (t - tv[c + 1]));
            float qp = quant255(p), qt = quant255(t);
            float d = qp - qt;                 // integer-valued
            a_mse += (unsigned)(d * d);        // exact (<= 65025 per px)
            sP[ly * SPITCH + lxq + c] = qp;
            sT[ly * SPITCH + lxq + c] = qt;
        }
    }

    // ---- halo ring: quantize-on-store (OOB -> quant(0); feeds only invalid outputs)
    for (int i = tid; i < HALO_N; i += 256) {
        int r, c;
        if (i < 420) { r = 32 + i / 42; c = i - (i / 42) * 42; }
        else         { int j = i - 420; r = j / 10; c = 32 + (j - (j / 10) * 10); }
        int gy = by0 + r, gx = bx0 + c;
        float p = 0.f, t = 0.f;
        if (gy < IMG_H && gx < IMG_W) {
            size_t gi = (size_t)gy * IMG_W + gx;
            p = P[gi];
            t = T[gi];
        }
        sP[r * SPITCH + c] = quant255(p);
        sT[r * SPITCH + c] = quant255(t);
    }
    __syncthreads();

    // ---- Phase D: horizontal 11-tap conv ----------------------------------
    // 252 tasks: (g, row, half).  g=0: sP -> (hP,hPP) pairs; g=1: sT -> (hT,hTT);
    // g=2: sP*sT -> hPT.  g<2 accumulators pack (val, val^2) per column ->
    // squares cost one FMUL in registers and stores are 16 STS.64 (per-half-warp
    // bank-complete -> conflict-free).
    if (tid < 252) {
        int g    = tid / 84;
        int u    = tid - g * 84;
        int row  = u % 42;
        int half = u / 42;                 // 0: cols 0-15, 1: cols 16-31
        int c0   = half * 16;

        if (g < 2) {
            const float* r0 = (g ? sT : sP) + row * SPITCH + c0;
            u64 acc[16];
            #pragma unroll
            for (int o = 0; o < 16; o++) acc[o] = 0ull;
            #pragma unroll
            for (int j = 0; j < 26; j++) {
                float x = r0[j];
                u64 v2 = pack2(x, x * x);
                #pragma unroll
                for (int o = 0; o < 16; o++) {
                    int k = j - o;
                    if (k >= 0 && k < 11) acc[o] = fma2_(w2[KSYM(k)], v2, acc[o]);
                }
            }
            float2* dst = (g ? h2b : h2a) + row * HP2 + c0;
            #pragma unroll
            for (int o = 0; o < 16; o++)
                *(u64*)&dst[o] = acc[o];
        } else {
            const float* rp = sP + row * SPITCH + c0;
            const float* rt = sT + row * SPITCH + c0;
            float win[9];                     // sliding pt window
            #pragma unroll
            for (int j = 0; j < 8; j++) win[j] = rp[j] * rt[j];
            u64 acc[8];
            #pragma unroll
            for (int o = 0; o < 8; o++) acc[o] = 0ull;
            #pragma unroll
            for (int j = 0; j < 18; j++) {
                win[(j + 8) % 9] = rp[j + 8] * rt[j + 8];
                u64 v = pack2(win[j % 9], win[(j + 8) % 9]);   // (pt[j], pt[j+8])
                #pragma unroll
                for (int o = 0; o < 8; o++) {
                    int k = j - o;
                    if (k >= 0 && k < 11) acc[o] = fma2_(w2[KSYM(k)], v, acc[o]);
                }
            }
            float* d = h1 + row * HP2;
            #pragma unroll
            for (int o = 0; o < 8; o++) {
                float lo, hi;
                unpack2(acc[o], lo, hi);
                d[c0 + o]     = lo;
                d[c0 + o + 8] = hi;
            }
        }
    }
    __syncthreads();

    // ---- Phase E: vertical 11-tap conv + SSIM (scatter form, 256 threads) -
    // accA = (m1, cpp), accB = (m2, ctt), accC = conv(hPT)
    {
        const float C1F = 6.5025f;    // (0.01*255)^2
        const float C2F = 58.5225f;   // (0.03*255)^2
        const int tx    = tid & 31;
        const int rbase = (tid >> 5) * 4;   // 0,4,...,28

        u64 accA[4], accB[4];
        float accC[4];
        #pragma unroll
        for (int r = 0; r < 4; r++) { accA[r] = 0ull; accB[r] = 0ull; accC[r] = 0.f; }

        #pragma unroll
        for (int j = 0; j < 14; j++) {
            int rr = rbase + j;
            u64 va   = *(const u64*)&h2a[rr * HP2 + tx];
            u64 vb   = *(const u64*)&h2b[rr * HP2 + tx];
            float vc = h1[rr * HP2 + tx];
            #pragma unroll
            for (int r = 0; r < 4; r++) {
                int k = j - r;
                if (k >= 0 && k < 11) {
                    accA[r] = fma2_(w2[KSYM(k)], va, accA[r]);
                    accB[r] = fma2_(w2[KSYM(k)], vb, accB[r]);
                    accC[r] = fmaf(wf[KSYM(k)], vc, accC[r]);
                }
            }
        }
        const bool xok = (bx0 + tx) < OUT_DIM;
        #pragma unroll
        for (int r = 0; r < 4; r++) {
            if (xok && (by0 + rbase + r) < OUT_DIM) {
                float m1, m2, cpp, ctt;
                unpack2(accA[r], m1, cpp);
                unpack2(accB[r], m2, ctt);
                float m1s = m1 * m1, m2s = m2 * m2, m12 = m1 * m2;
                float s1 = cpp - m1s, s2 = ctt - m2s, s12 = accC[r] - m12;
                float num = (2.0f * m12 + C1F) * (2.0f * s12 + C2F);
                float den = (m1s + m2s + C1F) * (s1 + s2 + C2F);
                a_ssim += __fdividef(num, den);
            }
        }
    }

    // ---- Phase F: block reduction + atomics -------------------------------
    float vals[9] = {a_l1, a_gh, a_gw, a_rng, a_sp, a_st, a_spp, a_stt, a_ssim};
    #pragma unroll
    for (int q = 0; q < 9; q++) {
        float v = vals[q];
        #pragma unroll
        for (int o = 16; o > 0; o >>= 1) v += __shfl_down_sync(0xffffffffu, v, o);
        vals[q] = v;
    }
    unsigned mm = a_mse;
    #pragma unroll
    for (int o = 16; o > 0; o >>= 1) mm += __shfl_down_sync(0xffffffffu, mm, o);

    int wid = tid >> 5, lane = tid & 31;
    if (lane == 0) {
        #pragma unroll
        for (int q = 0; q < 9; q++) s_redf[wid][q] = vals[q];
        s_redu[wid] = mm;
    }
    __syncthreads();
    if (tid < 32) {
        float v[9];
        #pragma unroll
        for (int q = 0; q < 9; q++) {
            float x = (tid < 8) ? s_redf[tid][q] : 0.f;
            #pragma unroll
            for (int o = 4; o > 0; o >>= 1) x += __shfl_down_sync(0xffffffffu, x, o);
            v[q] = x;
        }
        unsigned xm = (tid < 8) ? s_redu[tid] : 0u;
        #pragma unroll
        for (int o = 4; o > 0; o >>= 1) xm += __shfl_down_sync(0xffffffffu, xm, o);
        if (tid == 0) {
            atomicAdd(&g_l1,    (double)v[0]);
            atomicAdd(&g_gh,    (double)v[1]);
            atomicAdd(&g_gw,    (double)v[2]);
            atomicAdd(&g_range, (double)v[3]);
            atomicAdd(&g_sp[b], (double)v[4]);
            atomicAdd(&g_st[b], (double)v[5]);
            atomicAdd(&g_spp[b],(double)v[6]);
            atomicAdd(&g_stt[b],(double)v[7]);
            atomicAdd(&g_ssim,  (double)v[8]);
            atomicAdd(&g_mse[b], (unsigned long long)xm);
        }
    }

    // ---- Tail: last finished block finalizes + resets for next replay -----
    if (tid == 0) {
        __threadfence();
        unsigned prev = atomicAdd(&g_done, 1u);
        s_last = (prev == (unsigned)(NBLOCKS - 1));
    }
    __syncthreads();
    if (s_last && tid == 0) {
        const double n = (double)IMG_H * (double)IMG_W;
        double l1 = g_l1 / ((double)NB * n);
        double grad = g_gh / ((double)NB * (double)(IMG_H - 1) * (double)IMG_W)
                    + g_gw / ((double)NB * (double)IMG_H * (double)(IMG_W - 1));
        double energy = 0.0, dist = 0.0, psnr = 0.0;
        for (int i = 0; i < NB; i++) {
            double pm = g_sp[i] / n, tm = g_st[i] / n;
            energy += (pm - tm) * (pm - tm);
            double ps = sqrt(fmax((g_spp[i] - n * pm * pm) / (n - 1.0), 0.0));
            double ts = sqrt(fmax((g_stt[i] - n * tm * tm) / (n - 1.0), 0.0));
            dist += (ps - ts) * (ps - ts);
            double mse = (double)g_mse[i] / n;
            psnr += (mse == 0.0) ? 100.0 : 10.0 * log10(65025.0 / mse);
        }
        energy /= NB; dist /= NB; psnr /= NB;
        double range = g_range / ((double)NB * n);
        double phys = energy + 0.5 * dist + 0.1 * range;
        double ssim_mean = g_ssim / ((double)NB * (double)OUT_DIM * (double)OUT_DIM);
        ssim_mean = fmin(fmax(ssim_mean, 0.0), 1.0);
        double total = 1.0 * l1 + 0.15 * grad + 0.05 * phys + 0.1 * (1.0 - ssim_mean);
        out[0] = (float)total;
        out[1] = (float)psnr;
        out[2] = (float)ssim_mean;

        // reset accumulators so every graph replay starts from a clean state
        g_l1 = 0.0; g_gh = 0.0; g_gw = 0.0; g_range = 0.0; g_ssim = 0.0;
        for (int i = 0; i < NB; i++) {
            g_sp[i] = 0.0; g_st[i] = 0.0; g_spp[i] = 0.0; g_stt[i] = 0.0;
            g_mse[i] = 0ull;
        }
        g_done = 0u;
        __threadfence();
    }
}

extern "C" void kernel_launch(void* const* d_in, const int* in_sizes, int n_in,
                              void* d_out, int out_size)
{
    const float* pred = (const float*)d_in[0];
    const float* targ = (const float*)d_in[1];

    // Gaussian 11-tap (sigma=1.5), normalized in double like the reference
    Wt wv;
    double g[11], s = 0.0;
    for (int i = 0; i < 11; i++) { double d = i - 5.0; g[i] = exp(-(d * d) / 4.5); s += g[i]; }
    for (int i = 0; i < 11; i++) wv.w[i] = (float)(g[i] / s);

    dim3 grid(GRID_X, GRID_Y, NB);
    loss_fused<<<grid, 256>>>(pred, targ, (float*)d_out, wv);
}

// round 14
// speedup vs baseline: 2.0923x; 1.0638x over previous
#include <cuda_runtime.h>
#include <math.h>

#define IMG_H 2048
#define IMG_W 2048
#define NB 4
#define OUT_DIM 2038          // IMG - 10 (VALID 11x11)
#define TILE_O 32
#define TILE_I 42             // TILE_O + 10
#define SPITCH 45             // odd pitch -> conflict-free strided row access
#define HP2 33                // pitch in float2 units (h2a/h2b) / floats (h1)
#define GRID_X (IMG_W / TILE_O)
#define GRID_Y (IMG_H / TILE_O)
#define NBLOCKS (GRID_X * GRID_Y * NB)
#define HALO_N (TILE_I * TILE_I - TILE_O * TILE_O)   // 740

typedef unsigned long long u64;

// ---------------- global accumulators (self-resetting each launch) ----------
__device__ double g_comb, g_ssim;
__device__ double g_sp[NB], g_st[NB], g_spp[NB], g_stt[NB];
__device__ unsigned long long g_mse[NB];
__device__ unsigned int g_done;

struct Wt { float w[11]; float k_l1, k_g, k_rng; };

__device__ __forceinline__ u64 pack2(float lo, float hi) {
    u64 r; asm("mov.b64 %0, {%1,%2};" : "=l"(r) : "f"(lo), "f"(hi)); return r;
}
__device__ __forceinline__ void unpack2(u64 v, float& lo, float& hi) {
    asm("mov.b64 {%0,%1}, %2;" : "=f"(lo), "=f"(hi) : "l"(v));
}
__device__ __forceinline__ u64 fma2_(u64 a, u64 b, u64 c) {
    u64 d; asm("fma.rn.f32x2 %0, %1, %2, %3;" : "=l"(d) : "l"(a), "l"(b), "l"(c));
    return d;
}

// Fast quant: equivalent to reference floor-chain within <=2 ulp (see R10 note).
__device__ __forceinline__ float quant255(float x) {
    x = fminf(fmaxf(x, -1.0f), 1.0f);
    return floorf(fmaf(x, 127.5f, 127.5f));
}

// symmetric tap index: w[k] == w[10-k]
#define KSYM(k) ((k) < 6 ? (k) : 10 - (k))

__global__ __launch_bounds__(256, 4) void loss_fused(const float* __restrict__ pred,
                                                     const float* __restrict__ targ,
                                                     float* __restrict__ out,
                                                     Wt wp)
{
    __shared__ float  sP[TILE_I * SPITCH];   // QUANTIZED tile
    __shared__ float  sT[TILE_I * SPITCH];
    __shared__ float2 h2a[TILE_I * HP2 + 1]; // (hP,  hPP) pairs
    __shared__ float2 h2b[TILE_I * HP2 + 1]; // (hT,  hTT) pairs
    __shared__ float  h1 [TILE_I * HP2];     // hPT
    __shared__ float s_redf[8][8];
    __shared__ unsigned s_redu[8];
    __shared__ bool s_last;

    const int tid = threadIdx.x;
    const int b   = blockIdx.z;
    const int by0 = blockIdx.y * TILE_O;
    const int bx0 = blockIdx.x * TILE_O;
    const size_t ioff = (size_t)b * IMG_H * IMG_W;
    const float* P = pred + ioff;
    const float* T = targ + ioff;

    // 6 distinct Gaussian taps (w[k] = w[10-k])
    float wf[6];
    u64 w2[6];
    #pragma unroll
    for (int i = 0; i < 6; i++) { wf[i] = wp.w[i]; w2[i] = pack2(wf[i], wf[i]); }

    float a_l1 = 0.f, a_g = 0.f, a_rng = 0.f;
    float a_sp = 0.f, a_st = 0.f, a_spp = 0.f, a_stt = 0.f, a_ssim = 0.f;
    unsigned a_mse = 0u;

    // ---- Phase A (fused): owned 32x32 -> stats in registers + quantized store
    {
        const int ly  = tid >> 3;             // 0..31
        const int lxq = (tid & 7) * 4;        // 0,4,...,28
        const int gy = by0 + ly, gx = bx0 + lxq;
        const float* prow = P + (size_t)gy * IMG_W + gx;
        const float* trow = T + (size_t)gy * IMG_W + gx;
        float4 p4 = *(const float4*)prow;
        float4 t4 = *(const float4*)trow;
        const bool down_ok = (gy + 1) < IMG_H;
        float4 pd4 = down_ok ? *(const float4*)(prow + IMG_W) : p4;
        float4 td4 = down_ok ? *(const float4*)(trow + IMG_W) : t4;

        float pn = __shfl_down_sync(0xffffffffu, p4.x, 1);
        float tn = __shfl_down_sync(0xffffffffu, t4.x, 1);
        if ((tid & 7) == 7) {
            const bool rok = (gx + 4) < IMG_W;
            pn = rok ? prow[4] : 0.f;
            tn = rok ? trow[4] : 0.f;
        }
        float pv[5] = {p4.x, p4.y, p4.z, p4.w, pn};
        float tv[5] = {t4.x, t4.y, t4.z, t4.w, tn};
        float pd[4] = {pd4.x, pd4.y, pd4.z, pd4.w};
        float td[4] = {td4.x, td4.y, td4.z, td4.w};

        #pragma unroll
        for (int c = 0; c < 4; c++) {
            float p = pv[c], t = tv[c];
            a_l1  += fabsf(p - t);
            a_rng += fmaxf(fabsf(p) - 1.0f, 0.0f);
            a_sp  += p;  a_st  += t;
            a_spp += p * p;  a_stt += t * t;
            if (down_ok)            a_g += fabsf((p - pd[c]) - (t - td[c]));
            if (gx + c < IMG_W - 1) a_g += fabsf((p - pv[c + 1]) - (t - tv[c + 1]));
            float qp = quant255(p), qt = quant255(t);
            float d = qp - qt;                 // integer-valued
            a_mse += (unsigned)(d * d);        // exact (<= 65025 per px)
            sP[ly * SPITCH + lxq + c] = qp;
            sT[ly * SPITCH + lxq + c] = qt;
        }
    }

    // ---- halo ring: vectorized fast path for interior blocks --------------
    if ((bx0 + 41 < IMG_W) && (by0 + 41 < IMG_H)) {
        // 206 tasks: bottom strip 10 rows x 11 chunks (110), right strip
        // 32 rows x 3 chunks (96). Chunks at col 40 are float2, rest float4.
        if (tid < 206) {
            int r, c;
            if (tid < 110) { int rr = tid / 11; r = 32 + rr; c = (tid - rr * 11) * 4; }
            else           { int u = tid - 110; int rr = u / 3; r = rr; c = 32 + (u - rr * 3) * 4; }
            const size_t gbase = (size_t)(by0 + r) * IMG_W + (bx0 + c);
            float* dp = sP + r * SPITCH + c;
            float* dt = sT + r * SPITCH + c;
            if (c == 40) {
                float2 p2 = *(const float2*)(P + gbase);
                float2 t2 = *(const float2*)(T + gbase);
                dp[0] = quant255(p2.x); dp[1] = quant255(p2.y);
                dt[0] = quant255(t2.x); dt[1] = quant255(t2.y);
            } else {
                float4 p4 = *(const float4*)(P + gbase);
                float4 t4 = *(const float4*)(T + gbase);
                dp[0] = quant255(p4.x); dp[1] = quant255(p4.y);
                dp[2] = quant255(p4.z); dp[3] = quant255(p4.w);
                dt[0] = quant255(t4.x); dt[1] = quant255(t4.y);
                dt[2] = quant255(t4.z); dt[3] = quant255(t4.w);
            }
        }
    } else {
        // edge blocks: scalar guarded path (OOB -> quant(0); feeds only
        // invalid outputs)
        for (int i = tid; i < HALO_N; i += 256) {
            int r, c;
            if (i < 420) { r = 32 + i / 42; c = i - (i / 42) * 42; }
            else         { int j = i - 420; r = j / 10; c = 32 + (j - (j / 10) * 10); }
            int gy = by0 + r, gx = bx0 + c;
            float p = 0.f, t = 0.f;
            if (gy < IMG_H && gx < IMG_W) {
                size_t gi = (size_t)gy * IMG_W + gx;
                p = P[gi];
                t = T[gi];
            }
            sP[r * SPITCH + c] = quant255(p);
            sT[r * SPITCH + c] = quant255(t);
        }
    }
    __syncthreads();

    // ---- Phase D: horizontal 11-tap conv, UNIFIED branchless path ---------
    // 252 tasks: g=0: sP -> (hP,hPP); g=1: sT -> (hT,hTT); g=2: sP*sT -> hPT.
    // All tasks run the same 26-load / 16-accumulator / 11-tap loop; lane
    // packing is (a, a*b) with b=a for g<2 (squares) and b=t for g=2 (both
    // lanes = pt, store lo). Only the 16-store tail differs per g.
    if (tid < 252) {
        int g    = tid / 84;
        int u    = tid - g * 84;
        int row  = u % 42;
        int half = u / 42;                 // 0: cols 0-15, 1: cols 16-31
        int c0   = half * 16;
        const bool isPT = (g == 2);

        const float* rA = (g == 1 ? sT : sP) + row * SPITCH + c0;
        const float* rB = sT + row * SPITCH + c0;   // consumed only when isPT

        u64 acc[16];
        #pragma unroll
        for (int o = 0; o < 16; o++) acc[o] = 0ull;
        #pragma unroll
        for (int j = 0; j < 26; j++) {
            float a = rA[j];
            float bb = a;
            if (isPT) bb = rB[j];          // predicated LDS
            float x = a * bb;              // a^2 or p*t
            u64 v2 = pack2(isPT ? x : a, x);
            #pragma unroll
            for (int o = 0; o < 16; o++) {
                int k = j - o;
                if (k >= 0 && k < 11) acc[o] = fma2_(w2[KSYM(k)], v2, acc[o]);
            }
        }
        if (!isPT) {
            float2* dst = (g ? h2b : h2a) + row * HP2 + c0;
            #pragma unroll
            for (int o = 0; o < 16; o++)
                *(u64*)&dst[o] = acc[o];
        } else {
            float* d = h1 + row * HP2 + c0;
            #pragma unroll
            for (int o = 0; o < 16; o++) {
                float lo, hi;
                unpack2(acc[o], lo, hi);
                d[o] = lo;
            }
        }
    }
    __syncthreads();

    // ---- Phase E: vertical 11-tap conv + SSIM (scatter form, 256 threads) -
    // accA = (m1, cpp), accB = (m2, ctt), accC = conv(hPT)
    {
        const float C1F = 6.5025f;    // (0.01*255)^2
        const float C2F = 58.5225f;   // (0.03*255)^2
        const int tx    = tid & 31;
        const int rbase = (tid >> 5) * 4;   // 0,4,...,28

        u64 accA[4], accB[4];
        float accC[4];
        #pragma unroll
        for (int r = 0; r < 4; r++) { accA[r] = 0ull; accB[r] = 0ull; accC[r] = 0.f; }

        #pragma unroll
        for (int j = 0; j < 14; j++) {
            int rr = rbase + j;
            u64 va   = *(const u64*)&h2a[rr * HP2 + tx];
            u64 vb   = *(const u64*)&h2b[rr * HP2 + tx];
            float vc = h1[rr * HP2 + tx];
            #pragma unroll
            for (int r = 0; r < 4; r++) {
                int k = j - r;
                if (k >= 0 && k < 11) {
                    accA[r] = fma2_(w2[KSYM(k)], va, accA[r]);
                    accB[r] = fma2_(w2[KSYM(k)], vb, accB[r]);
                    accC[r] = fmaf(wf[KSYM(k)], vc, accC[r]);
                }
            }
        }
        const bool xok = (bx0 + tx) < OUT_DIM;
        #pragma unroll
        for (int r = 0; r < 4; r++) {
            if (xok && (by0 + rbase + r) < OUT_DIM) {
                float m1, m2, cpp, ctt;
                unpack2(accA[r], m1, cpp);
                unpack2(accB[r], m2, ctt);
                float m1s = m1 * m1, m2s = m2 * m2, m12 = m1 * m2;
                float s1 = cpp - m1s, s2 = ctt - m2s, s12 = accC[r] - m12;
                float num = (2.0f * m12 + C1F) * (2.0f * s12 + C2F);
                float den = (m1s + m2s + C1F) * (s1 + s2 + C2F);
                a_ssim += __fdividef(num, den);
            }
        }
    }

    // ---- Phase F: block reduction + atomics -------------------------------
    // l1/grad/range appear only inside `total` -> pre-scaled merge into comb.
    float comb = fmaf(a_l1, wp.k_l1, fmaf(a_g, wp.k_g, a_rng * wp.k_rng));
    float vals[6] = {comb, a_sp, a_st, a_spp, a_stt, a_ssim};
    #pragma unroll
    for (int q = 0; q < 6; q++) {
        float v = vals[q];
        #pragma unroll
        for (int o = 16; o > 0; o >>= 1) v += __shfl_down_sync(0xffffffffu, v, o);
        vals[q] = v;
    }
    unsigned mm = __reduce_add_sync(0xffffffffu, a_mse);

    int wid = tid >> 5, lane = tid & 31;
    if (lane == 0) {
        #pragma unroll
        for (int q = 0; q < 6; q++) s_redf[wid][q] = vals[q];
        s_redu[wid] = mm;
    }
    __syncthreads();
    if (tid < 32) {
        float v[6];
        #pragma unroll
        for (int q = 0; q < 6; q++) {
            float x = (tid < 8) ? s_redf[tid][q] : 0.f;
            #pragma unroll
            for (int o = 4; o > 0; o >>= 1) x += __shfl_down_sync(0xffffffffu, x, o);
            v[q] = x;
        }
        unsigned xm = (tid < 8) ? s_redu[tid] : 0u;
        #pragma unroll
        for (int o = 4; o > 0; o >>= 1) xm += __shfl_down_sync(0xffffffffu, xm, o);
        if (tid == 0) {
            atomicAdd(&g_comb,  (double)v[0]);
            atomicAdd(&g_sp[b], (double)v[1]);
            atomicAdd(&g_st[b], (double)v[2]);
            atomicAdd(&g_spp[b],(double)v[3]);
            atomicAdd(&g_stt[b],(double)v[4]);
            atomicAdd(&g_ssim,  (double)v[5]);
            atomicAdd(&g_mse[b], (unsigned long long)xm);
        }
    }

    // ---- Tail: last finished block finalizes + resets for next replay -----
    if (tid == 0) {
        __threadfence();
        unsigned prev = atomicAdd(&g_done, 1u);
        s_last = (prev == (unsigned)(NBLOCKS - 1));
    }
    __syncthreads();
    if (s_last && tid == 0) {
        const double n = (double)IMG_H * (double)IMG_W;
        double energy = 0.0, dist = 0.0, psnr = 0.0;
        for (int i = 0; i < NB; i++) {
            double pm = g_sp[i] / n, tm = g_st[i] / n;
            energy += (pm - tm) * (pm - tm);
            double ps = sqrt(fmax((g_spp[i] - n * pm * pm) / (n - 1.0), 0.0));
            double ts = sqrt(fmax((g_stt[i] - n * tm * tm) / (n - 1.0), 0.0));
            dist += (ps - ts) * (ps - ts);
            double mse = (double)g_mse[i] / n;
            psnr += (mse == 0.0) ? 100.0 : 10.0 * log10(65025.0 / mse);
        }
        energy /= NB; dist /= NB; psnr /= NB;
        double ssim_mean = g_ssim / ((double)NB * (double)OUT_DIM * (double)OUT_DIM);
        ssim_mean = fmin(fmax(ssim_mean, 0.0), 1.0);
        double total = g_comb + 0.05 * (energy + 0.5 * dist) + 0.1 * (1.0 - ssim_mean);
        out[0] = (float)total;
        out[1] = (float)psnr;
        out[2] = (float)ssim_mean;

        // reset accumulators so every graph replay starts from a clean state
        g_comb = 0.0; g_ssim = 0.0;
        for (int i = 0; i < NB; i++) {
            g_sp[i] = 0.0; g_st[i] = 0.0; g_spp[i] = 0.0; g_stt[i] = 0.0;
            g_mse[i] = 0ull;
        }
        g_done = 0u;
        __threadfence();
    }
}

extern "C" void kernel_launch(void* const* d_in, const int* in_sizes, int n_in,
                              void* d_out, int out_size)
{
    const float* pred = (const float*)d_in[0];
    const float* targ = (const float*)d_in[1];

    // Gaussian 11-tap (sigma=1.5), normalized in double like the reference
    Wt wv;
    double g[11], s = 0.0;
    for (int i = 0; i < 11; i++) { double d = i - 5.0; g[i] = exp(-(d * d) / 4.5); s += g[i]; }
    for (int i = 0; i < 11; i++) wv.w[i] = (float)(g[i] / s);

    const double n = (double)IMG_H * (double)IMG_W;
    wv.k_l1  = (float)(1.0   / ((double)NB * n));                         // ALPHA*l1
    wv.k_g   = (float)(0.15  / ((double)NB * (double)(IMG_H - 1) * IMG_W)); // BETA*(gh+gw); (H-1)*W == H*(W-1)
    wv.k_rng = (float)(0.005 / ((double)NB * n));                         // GAMMA*0.1*range

    dim3 grid(GRID_X, GRID_Y, NB);
    loss_fused<<<grid, 256>>>(pred, targ, (float*)d_out, wv);
}

// round 15
// speedup vs baseline: 2.1600x; 1.0323x over previous
#include <cuda_runtime.h>
#include <math.h>

#define IMG_H 2048
#define IMG_W 2048
#define NB 4
#define OUT_DIM 2038          // IMG - 10 (VALID 11x11)
#define TILE_O 32
#define TILE_I 42             // TILE_O + 10
#define SPITCH 44             // mult-of-4 pitch -> LDS.128/STS.128 everywhere
#define HP4 33                // pitch of h4 (float4 units) and h1 (floats)
#define GRID_X (IMG_W / TILE_O)
#define GRID_Y (IMG_H / TILE_O)
#define NBLOCKS (GRID_X * GRID_Y * NB)
#define HALO_N (TILE_I * TILE_I - TILE_O * TILE_O)   // 740

typedef unsigned long long u64;

// ---------------- global accumulators (self-resetting each launch) ----------
__device__ double g_comb, g_ssim;
__device__ double g_sp[NB], g_st[NB], g_spp[NB], g_stt[NB];
__device__ unsigned long long g_mse[NB];
__device__ unsigned int g_done;

struct Wt { float w[11]; float k_l1, k_g, k_rng; };

__device__ __forceinline__ u64 pack2(float lo, float hi) {
    u64 r; asm("mov.b64 %0, {%1,%2};" : "=l"(r) : "f"(lo), "f"(hi)); return r;
}
__device__ __forceinline__ void unpack2(u64 v, float& lo, float& hi) {
    asm("mov.b64 {%0,%1}, %2;" : "=f"(lo), "=f"(hi) : "l"(v));
}
__device__ __forceinline__ u64 fma2_(u64 a, u64 b, u64 c) {
    u64 d; asm("fma.rn.f32x2 %0, %1, %2, %3;" : "=l"(d) : "l"(a), "l"(b), "l"(c));
    return d;
}

// Fast quant: equivalent to reference floor-chain within <=2 ulp (see R10 note).
__device__ __forceinline__ float quant255(float x) {
    x = fminf(fmaxf(x, -1.0f), 1.0f);
    return floorf(fmaf(x, 127.5f, 127.5f));
}

// symmetric tap index: w[k] == w[10-k]
#define KSYM(k) ((k) < 6 ? (k) : 10 - (k))

__global__ __launch_bounds__(256, 4) void loss_fused(const float* __restrict__ pred,
                                                     const float* __restrict__ targ,
                                                     float* __restrict__ out,
                                                     Wt wp)
{
    __shared__ float  sP[TILE_I * SPITCH];   // QUANTIZED tile
    __shared__ float  sT[TILE_I * SPITCH];
    __shared__ float4 h4[TILE_I * HP4];      // (hP, hPP, hT, hTT)
    __shared__ float  h1[TILE_I * HP4];      // hPT
    __shared__ float s_redf[8][8];
    __shared__ unsigned s_redu[8];
    __shared__ bool s_last;

    const int tid = threadIdx.x;
    const int b   = blockIdx.z;
    const int by0 = blockIdx.y * TILE_O;
    const int bx0 = blockIdx.x * TILE_O;
    const size_t ioff = (size_t)b * IMG_H * IMG_W;
    const float* P = pred + ioff;
    const float* T = targ + ioff;

    // 6 distinct Gaussian taps (w[k] = w[10-k])
    float wf[6];
    u64 w2[6];
    #pragma unroll
    for (int i = 0; i < 6; i++) { wf[i] = wp.w[i]; w2[i] = pack2(wf[i], wf[i]); }

    float a_l1 = 0.f, a_g = 0.f, a_rng = 0.f;
    float a_sp = 0.f, a_st = 0.f, a_spp = 0.f, a_stt = 0.f, a_ssim = 0.f;
    unsigned a_mse = 0u;

    // ---- Phase A (fused): owned 32x32 -> stats in registers + quantized store
    {
        const int ly  = tid >> 3;             // 0..31
        const int lxq = (tid & 7) * 4;        // 0,4,...,28
        const int gy = by0 + ly, gx = bx0 + lxq;
        const float* prow = P + (size_t)gy * IMG_W + gx;
        const float* trow = T + (size_t)gy * IMG_W + gx;
        float4 p4 = *(const float4*)prow;
        float4 t4 = *(const float4*)trow;
        const bool down_ok = (gy + 1) < IMG_H;
        float4 pd4 = down_ok ? *(const float4*)(prow + IMG_W) : p4;
        float4 td4 = down_ok ? *(const float4*)(trow + IMG_W) : t4;

        float pn = __shfl_down_sync(0xffffffffu, p4.x, 1);
        float tn = __shfl_down_sync(0xffffffffu, t4.x, 1);
        if ((tid & 7) == 7) {
            const bool rok = (gx + 4) < IMG_W;
            pn = rok ? prow[4] : 0.f;
            tn = rok ? trow[4] : 0.f;
        }
        float pv[5] = {p4.x, p4.y, p4.z, p4.w, pn};
        float tv[5] = {t4.x, t4.y, t4.z, t4.w, tn};
        float pd[4] = {pd4.x, pd4.y, pd4.z, pd4.w};
        float td[4] = {td4.x, td4.y, td4.z, td4.w};

        float qp[4], qt[4];
        #pragma unroll
        for (int c = 0; c < 4; c++) {
            float p = pv[c], t = tv[c];
            a_l1  += fabsf(p - t);
            a_rng += fmaxf(fabsf(p) - 1.0f, 0.0f);
            a_sp  += p;  a_st  += t;
            a_spp += p * p;  a_stt += t * t;
            if (down_ok)            a_g += fabsf((p - pd[c]) - (t - td[c]));
            if (gx + c < IMG_W - 1) a_g += fabsf((p - pv[c + 1]) - (t - tv[c + 1]));
            qp[c] = quant255(p); qt[c] = quant255(t);
            float d = qp[c] - qt[c];           // integer-valued
            a_mse += (unsigned)(d * d);        // exact (<= 65025 per px)
        }
        *(float4*)&sP[ly * SPITCH + lxq] = make_float4(qp[0], qp[1], qp[2], qp[3]);
        *(float4*)&sT[ly * SPITCH + lxq] = make_float4(qt[0], qt[1], qt[2], qt[3]);
    }

    // ---- halo ring ---------------------------------------------------------
    if ((bx0 + 41 < IMG_W) && (by0 + 41 < IMG_H)) {
        // interior: 206 uniform float4 chunk tasks. Bottom strip 10 rows x 11
        // chunks (c=0..40), right strip 32 rows x 3 chunks (c=32,36,40).
        // Chunks at c=40 spill into row padding words 42,43 (harmless); their
        // global reads stay in-bounds for interior blocks (bx0+43 < W).
        if (tid < 206) {
            int r, c;
            if (tid < 110) { int rr = tid / 11; r = 32 + rr; c = (tid - rr * 11) * 4; }
            else           { int u = tid - 110; int rr = u / 3; r = rr; c = 32 + (u - rr * 3) * 4; }
            const size_t gbase = (size_t)(by0 + r) * IMG_W + (bx0 + c);
            float4 p4 = *(const float4*)(P + gbase);
            float4 t4 = *(const float4*)(T + gbase);
            *(float4*)&sP[r * SPITCH + c] =
                make_float4(quant255(p4.x), quant255(p4.y), quant255(p4.z), quant255(p4.w));
            *(float4*)&sT[r * SPITCH + c] =
                make_float4(quant255(t4.x), quant255(t4.y), quant255(t4.z), quant255(t4.w));
        }
    } else {
        // edge blocks: scalar guarded path (OOB -> quant(0); feeds only
        // invalid outputs)
        for (int i = tid; i < HALO_N; i += 256) {
            int r, c;
            if (i < 420) { r = 32 + i / 42; c = i - (i / 42) * 42; }
            else         { int j = i - 420; r = j / 10; c = 32 + (j - (j / 10) * 10); }
            int gy = by0 + r, gx = bx0 + c;
            float p = 0.f, t = 0.f;
            if (gy < IMG_H && gx < IMG_W) {
                size_t gi = (size_t)gy * IMG_W + gx;
                p = P[gi];
                t = T[gi];
            }
            sP[r * SPITCH + c] = quant255(p);
            sT[r * SPITCH + c] = quant255(t);
        }
    }
    __syncthreads();

    // ---- Phase D: horizontal 11-tap conv, unified path, float4 loads ------
    // 252 tasks: g=0: sP -> h4.xy (hP,hPP); g=1: sT -> h4.zw (hT,hTT);
    // g=2: sP*sT -> h1. Lane packing (a, a*b): b=a for squares, b=t for PT.
    if (tid < 252) {
        int g    = tid / 84;
        int u    = tid - g * 84;
        int row  = u % 42;
        int half = u / 42;                 // 0: cols 0-15, 1: cols 16-31
        int c0   = half * 16;
        const bool isPT = (g == 2);

        const float* rA = (g == 1 ? sT : sP) + row * SPITCH + c0;
        const float* rB = sT + row * SPITCH + c0;   // consumed only when isPT

        u64 acc[16];
        #pragma unroll
        for (int o = 0; o < 16; o++) acc[o] = 0ull;
        #pragma unroll
        for (int jj = 0; jj < 7; jj++) {
            float4 a4 = *(const float4*)(rA + 4 * jj);
            float4 b4 = a4;
            if (isPT) b4 = *(const float4*)(rB + 4 * jj);   // predicated LDS.128
            const float ae[4] = {a4.x, a4.y, a4.z, a4.w};
            const float be[4] = {b4.x, b4.y, b4.z, b4.w};
            #pragma unroll
            for (int e = 0; e < 4; e++) {
                const int j = 4 * jj + e;
                if (j < 26) {
                    float a = ae[e];
                    float x = a * be[e];           // a^2 or p*t
                    u64 v2 = pack2(isPT ? x : a, x);
                    #pragma unroll
                    for (int o = 0; o < 16; o++) {
                        int k = j - o;
                        if (k >= 0 && k < 11) acc[o] = fma2_(w2[KSYM(k)], v2, acc[o]);
                    }
                }
            }
        }
        if (!isPT) {
            float* dst = (float*)&h4[row * HP4 + c0] + 2 * g;   // .xy or .zw
            #pragma unroll
            for (int o = 0; o < 16; o++)
                *(u64*)(dst + 4 * o) = acc[o];                  // STS.64
        } else {
            float* d = h1 + row * HP4 + c0;
            #pragma unroll
            for (int o = 0; o < 16; o++) {
                float lo, hi;
                unpack2(acc[o], lo, hi);
                d[o] = lo;
            }
        }
    }
    __syncthreads();

    // ---- Phase E: vertical 11-tap conv + SSIM (scatter form, 256 threads) -
    // One LDS.128 delivers (hP,hPP,hT,hTT); accA=(m1,cpp), accB=(m2,ctt).
    {
        const float C1F = 6.5025f;    // (0.01*255)^2
        const float C2F = 58.5225f;   // (0.03*255)^2
        const int tx    = tid & 31;
        const int rbase = (tid >> 5) * 4;   // 0,4,...,28

        u64 accA[4], accB[4];
        float accC[4];
        #pragma unroll
        for (int r = 0; r < 4; r++) { accA[r] = 0ull; accB[r] = 0ull; accC[r] = 0.f; }

        #pragma unroll
        for (int j = 0; j < 14; j++) {
            int rr = rbase + j;
            float4 v4 = h4[rr * HP4 + tx];
            u64 va = pack2(v4.x, v4.y);
            u64 vb = pack2(v4.z, v4.w);
            float vc = h1[rr * HP4 + tx];
            #pragma unroll
            for (int r = 0; r < 4; r++) {
                int k = j - r;
                if (k >= 0 && k < 11) {
                    accA[r] = fma2_(w2[KSYM(k)], va, accA[r]);
                    accB[r] = fma2_(w2[KSYM(k)], vb, accB[r]);
                    accC[r] = fmaf(wf[KSYM(k)], vc, accC[r]);
                }
            }
        }
        const bool xok = (bx0 + tx) < OUT_DIM;
        #pragma unroll
        for (int r = 0; r < 4; r++) {
            if (xok && (by0 + rbase + r) < OUT_DIM) {
                float m1, m2, cpp, ctt;
                unpack2(accA[r], m1, cpp);
                unpack2(accB[r], m2, ctt);
                float m1s = m1 * m1, m2s = m2 * m2, m12 = m1 * m2;
                float s1 = cpp - m1s, s2 = ctt - m2s, s12 = accC[r] - m12;
                float num = (2.0f * m12 + C1F) * (2.0f * s12 + C2F);
                float den = (m1s + m2s + C1F) * (s1 + s2 + C2F);
                a_ssim += __fdividef(num, den);
            }
        }
    }

    // ---- Phase F: block reduction + atomics -------------------------------
    float comb = fmaf(a_l1, wp.k_l1, fmaf(a_g, wp.k_g, a_rng * wp.k_rng));
    float vals[6] = {comb, a_sp, a_st, a_spp, a_stt, a_ssim};
    #pragma unroll
    for (int q = 0; q < 6; q++) {
        float v = vals[q];
        #pragma unroll
        for (int o = 16; o > 0; o >>= 1) v += __shfl_down_sync(0xffffffffu, v, o);
        vals[q] = v;
    }
    unsigned mm = __reduce_add_sync(0xffffffffu, a_mse);

    int wid = tid >> 5, lane = tid & 31;
    if (lane == 0) {
        #pragma unroll
        for (int q = 0; q < 6; q++) s_redf[wid][q] = vals[q];
        s_redu[wid] = mm;
    }
    __syncthreads();
    if (tid < 32) {
        float v[6];
        #pragma unroll
        for (int q = 0; q < 6; q++) {
            float x = (tid < 8) ? s_redf[tid][q] : 0.f;
            #pragma unroll
            for (int o = 4; o > 0; o >>= 1) x += __shfl_down_sync(0xffffffffu, x, o);
            v[q] = x;
        }
        unsigned xm = (tid < 8) ? s_redu[tid] : 0u;
        #pragma unroll
        for (int o = 4; o > 0; o >>= 1) xm += __shfl_down_sync(0xffffffffu, xm, o);
        if (tid == 0) {
            atomicAdd(&g_comb,  (double)v[0]);
            atomicAdd(&g_sp[b], (double)v[1]);
            atomicAdd(&g_st[b], (double)v[2]);
            atomicAdd(&g_spp[b],(double)v[3]);
            atomicAdd(&g_stt[b],(double)v[4]);
            atomicAdd(&g_ssim,  (double)v[5]);
            atomicAdd(&g_mse[b], (unsigned long long)xm);
        }
    }

    // ---- Tail: last finished block finalizes + resets for next replay -----
    if (tid == 0) {
        __threadfence();
        unsigned prev = atomicAdd(&g_done, 1u);
        s_last = (prev == (unsigned)(NBLOCKS - 1));
    }
    __syncthreads();
    if (s_last && tid == 0) {
        const double n = (double)IMG_H * (double)IMG_W;
        double energy = 0.0, dist = 0.0, psnr = 0.0;
        for (int i = 0; i < NB; i++) {
            double pm = g_sp[i] / n, tm = g_st[i] / n;
            energy += (pm - tm) * (pm - tm);
            double ps = sqrt(fmax((g_spp[i] - n * pm * pm) / (n - 1.0), 0.0));
            double ts = sqrt(fmax((g_stt[i] - n * tm * tm) / (n - 1.0), 0.0));
            dist += (ps - ts) * (ps - ts);
            double mse = (double)g_mse[i] / n;
            psnr += (mse == 0.0) ? 100.0 : 10.0 * log10(65025.0 / mse);
        }
        energy /= NB; dist /= NB; psnr /= NB;
        double ssim_mean = g_ssim / ((double)NB * (double)OUT_DIM * (double)OUT_DIM);
        ssim_mean = fmin(fmax(ssim_mean, 0.0), 1.0);
        double total = g_comb + 0.05 * (energy + 0.5 * dist) + 0.1 * (1.0 - ssim_mean);
        out[0] = (float)total;
        out[1] = (float)psnr;
        out[2] = (float)ssim_mean;

        // reset accumulators so every graph replay starts from a clean state
        g_comb = 0.0; g_ssim = 0.0;
        for (int i = 0; i < NB; i++) {
            g_sp[i] = 0.0; g_st[i] = 0.0; g_spp[i] = 0.0; g_stt[i] = 0.0;
            g_mse[i] = 0ull;
        }
        g_done = 0u;
        __threadfence();
    }
}

extern "C" void kernel_launch(void* const* d_in, const int* in_sizes, int n_in,
                              void* d_out, int out_size)
{
    const float* pred = (const float*)d_in[0];
    const float* targ = (const float*)d_in[1];

    // Gaussian 11-tap (sigma=1.5), normalized in double like the reference
    Wt wv;
    double g[11], s = 0.0;
    for (int i = 0; i < 11; i++) { double d = i - 5.0; g[i] = exp(-(d * d) / 4.5); s += g[i]; }
    for (int i = 0; i < 11; i++) wv.w[i] = (float)(g[i] / s);

    const double n = (double)IMG_H * (double)IMG_W;
    wv.k_l1  = (float)(1.0   / ((double)NB * n));                           // ALPHA*l1
    wv.k_g   = (float)(0.15  / ((double)NB * (double)(IMG_H - 1) * IMG_W)); // BETA*(gh+gw)
    wv.k_rng = (float)(0.005 / ((double)NB * n));                           // GAMMA*0.1*range

    dim3 grid(GRID_X, GRID_Y, NB);
    loss_fused<<<grid, 256>>>(pred, targ, (float*)d_out, wv);
}

// round 16
// speedup vs baseline: 2.4236x; 1.1220x over previous
#include <cuda_runtime.h>
#include <math.h>

#define IMG_H 2048
#define IMG_W 2048
#define NB 4
#define OUT_DIM 2038          // IMG - 10 (VALID 11x11)
#define TILE_O 32
#define TILE_I 42             // TILE_O + 10
#define SPITCH 44             // mult-of-4 pitch -> LDS.128/STS.128 everywhere
#define HP4 33                // pitch of h4 (float4 units)
#define GRID_X (IMG_W / TILE_O)
#define GRID_Y (IMG_H / TILE_O)
#define NBLOCKS (GRID_X * GRID_Y * NB)
#define HALO_N (TILE_I * TILE_I - TILE_O * TILE_O)   // 740

typedef unsigned long long u64;

// ---------------- global accumulators (self-resetting each launch) ----------
__device__ double g_comb, g_ssim;
__device__ double g_sp[NB], g_st[NB], g_spp[NB], g_stt[NB];
__device__ unsigned long long g_mse[NB];
__device__ unsigned int g_done;

struct Wt { float w[11]; float k_l1, k_g, k_rng; };

__device__ __forceinline__ u64 pack2(float lo, float hi) {
    u64 r; asm("mov.b64 %0, {%1,%2};" : "=l"(r) : "f"(lo), "f"(hi)); return r;
}
__device__ __forceinline__ void unpack2(u64 v, float& lo, float& hi) {
    asm("mov.b64 {%0,%1}, %2;" : "=f"(lo), "=f"(hi) : "l"(v));
}
__device__ __forceinline__ u64 fma2_(u64 a, u64 b, u64 c) {
    u64 d; asm("fma.rn.f32x2 %0, %1, %2, %3;" : "=l"(d) : "l"(a), "l"(b), "l"(c));
    return d;
}

// Fast quant: equivalent to reference floor-chain within <=2 ulp (see R10 note).
__device__ __forceinline__ float quant255(float x) {
    x = fminf(fmaxf(x, -1.0f), 1.0f);
    return floorf(fmaf(x, 127.5f, 127.5f));
}

// symmetric tap index: w[k] == w[10-k]
#define KSYM(k) ((k) < 6 ? (k) : 10 - (k))

__global__ __launch_bounds__(256, 4) void loss_fused(const float* __restrict__ pred,
                                                     const float* __restrict__ targ,
                                                     float* __restrict__ out,
                                                     Wt wp)
{
    // sU = qp+qt, sV = qp-qt (quantized sum / difference planes).
    // SSIM identity: with cu=conv(u), cv=conv(v), cuu=conv(u^2), cvv=conv(v^2):
    //   2*m1m2        = (cu^2 - cv^2)/2      m1^2+m2^2          = (cu^2 + cv^2)/2
    //   2*conv(pt)    = (cuu - cvv)/2        conv(pp)+conv(tt)  = (cuu + cvv)/2
    // -> 4 conv fields instead of 5 (PT path eliminated).
    __shared__ float  sU[TILE_I * SPITCH];
    __shared__ float  sV[TILE_I * SPITCH];
    __shared__ float4 h4[TILE_I * HP4];      // (cu, cuu, cv, cvv) per column
    __shared__ float s_redf[8][8];
    __shared__ unsigned s_redu[8];
    __shared__ bool s_last;

    const int tid = threadIdx.x;
    const int b   = blockIdx.z;
    const int by0 = blockIdx.y * TILE_O;
    const int bx0 = blockIdx.x * TILE_O;
    const size_t ioff = (size_t)b * IMG_H * IMG_W;
    const float* P = pred + ioff;
    const float* T = targ + ioff;

    // 6 distinct Gaussian taps (w[k] = w[10-k])
    u64 w2[6];
    #pragma unroll
    for (int i = 0; i < 6; i++) w2[i] = pack2(wp.w[i], wp.w[i]);

    float a_l1 = 0.f, a_g = 0.f, a_rng = 0.f;
    float a_sp = 0.f, a_st = 0.f, a_spp = 0.f, a_stt = 0.f, a_ssim = 0.f;
    unsigned a_mse = 0u;

    // ---- Phase A (fused): owned 32x32 -> stats in registers + u/v store ----
    {
        const int ly  = tid >> 3;             // 0..31
        const int lxq = (tid & 7) * 4;        // 0,4,...,28
        const int gy = by0 + ly, gx = bx0 + lxq;
        const float* prow = P + (size_t)gy * IMG_W + gx;
        const float* trow = T + (size_t)gy * IMG_W + gx;
        float4 p4 = *(const float4*)prow;
        float4 t4 = *(const float4*)trow;
        const bool down_ok = (gy + 1) < IMG_H;
        float4 pd4 = down_ok ? *(const float4*)(prow + IMG_W) : p4;
        float4 td4 = down_ok ? *(const float4*)(trow + IMG_W) : t4;

        float pn = __shfl_down_sync(0xffffffffu, p4.x, 1);
        float tn = __shfl_down_sync(0xffffffffu, t4.x, 1);
        if ((tid & 7) == 7) {
            const bool rok = (gx + 4) < IMG_W;
            pn = rok ? prow[4] : 0.f;
            tn = rok ? trow[4] : 0.f;
        }
        float pv[5] = {p4.x, p4.y, p4.z, p4.w, pn};
        float tv[5] = {t4.x, t4.y, t4.z, t4.w, tn};
        float pd[4] = {pd4.x, pd4.y, pd4.z, pd4.w};
        float td[4] = {td4.x, td4.y, td4.z, td4.w};

        float qu[4], qv[4];
        #pragma unroll
        for (int c = 0; c < 4; c++) {
            float p = pv[c], t = tv[c];
            a_l1  += fabsf(p - t);
            a_rng += fmaxf(fabsf(p) - 1.0f, 0.0f);
            a_sp  += p;  a_st  += t;
            a_spp += p * p;  a_stt += t * t;
            if (down_ok)            a_g += fabsf((p - pd[c]) - (t - td[c]));
            if (gx + c < IMG_W - 1) a_g += fabsf((p - pv[c + 1]) - (t - tv[c + 1]));
            float qp = quant255(p), qt = quant255(t);
            float d = qp - qt;                 // integer-valued = v
            a_mse += (unsigned)(d * d);        // exact (<= 65025 per px)
            qu[c] = qp + qt;
            qv[c] = d;
        }
        *(float4*)&sU[ly * SPITCH + lxq] = make_float4(qu[0], qu[1], qu[2], qu[3]);
        *(float4*)&sV[ly * SPITCH + lxq] = make_float4(qv[0], qv[1], qv[2], qv[3]);
    }

    // ---- halo ring ---------------------------------------------------------
    if ((bx0 + 41 < IMG_W) && (by0 + 41 < IMG_H)) {
        // interior: 206 uniform float4 chunk tasks. Bottom strip 10 rows x 11
        // chunks (c=0..40), right strip 32 rows x 3 chunks (c=32,36,40).
        // Chunks at c=40 spill into row padding words 42,43 (harmless).
        if (tid < 206) {
            int r, c;
            if (tid < 110) { int rr = tid / 11; r = 32 + rr; c = (tid - rr * 11) * 4; }
            else           { int u = tid - 110; int rr = u / 3; r = rr; c = 32 + (u - rr * 3) * 4; }
            const size_t gbase = (size_t)(by0 + r) * IMG_W + (bx0 + c);
            float4 p4 = *(const float4*)(P + gbase);
            float4 t4 = *(const float4*)(T + gbase);
            float qp[4] = {quant255(p4.x), quant255(p4.y), quant255(p4.z), quant255(p4.w)};
            float qt[4] = {quant255(t4.x), quant255(t4.y), quant255(t4.z), quant255(t4.w)};
            *(float4*)&sU[r * SPITCH + c] =
                make_float4(qp[0] + qt[0], qp[1] + qt[1], qp[2] + qt[2], qp[3] + qt[3]);
            *(float4*)&sV[r * SPITCH + c] =
                make_float4(qp[0] - qt[0], qp[1] - qt[1], qp[2] - qt[2], qp[3] - qt[3]);
        }
    } else {
        // edge blocks: scalar guarded path (OOB -> quant(0); feeds only
        // invalid outputs)
        for (int i = tid; i < HALO_N; i += 256) {
            int r, c;
            if (i < 420) { r = 32 + i / 42; c = i - (i / 42) * 42; }
            else         { int j = i - 420; r = j / 10; c = 32 + (j - (j / 10) * 10); }
            int gy = by0 + r, gx = bx0 + c;
            float p = 0.f, t = 0.f;
            if (gy < IMG_H && gx < IMG_W) {
                size_t gi = (size_t)gy * IMG_W + gx;
                p = P[gi];
                t = T[gi];
            }
            float qp = quant255(p), qt = quant255(t);
            sU[r * SPITCH + c] = qp + qt;
            sV[r * SPITCH + c] = qp - qt;
        }
    }
    __syncthreads();

    // ---- Phase D: horizontal 11-tap conv, 168 branchless tasks ------------
    // g=0: sU -> h4.xy (cu, cuu); g=1: sV -> h4.zw (cv, cvv).
    // Lane packing (a, a^2): one fma2 convolves value and square together.
    if (tid < 168) {
        int g    = tid / 84;
        int u    = tid - g * 84;
        int row  = u % 42;
        int half = u / 42;                 // 0: cols 0-15, 1: cols 16-31
        int c0   = half * 16;

        const float* rA = (g ? sV : sU) + row * SPITCH + c0;

        u64 acc[16];
        #pragma unroll
        for (int o = 0; o < 16; o++) acc[o] = 0ull;
        #pragma unroll
        for (int jj = 0; jj < 7; jj++) {
            float4 a4 = *(const float4*)(rA + 4 * jj);
            const float ae[4] = {a4.x, a4.y, a4.z, a4.w};
            #pragma unroll
            for (int e = 0; e < 4; e++) {
                const int j = 4 * jj + e;
                if (j < 26) {
                    float a = ae[e];
                    u64 v2 = pack2(a, a * a);
                    #pragma unroll
                    for (int o = 0; o < 16; o++) {
                        int k = j - o;
                        if (k >= 0 && k < 11) acc[o] = fma2_(w2[KSYM(k)], v2, acc[o]);
                    }
                }
            }
        }
        float* dst = (float*)&h4[row * HP4 + c0] + 2 * g;   // .xy or .zw
        #pragma unroll
        for (int o = 0; o < 16; o++)
            *(u64*)(dst + 4 * o) = acc[o];                  // STS.64
    }
    __syncthreads();

    // ---- Phase E: vertical 11-tap conv + SSIM (scatter form, 256 threads) -
    // One LDS.128 delivers (cu,cuu,cv,cvv); accA=(CU,CUU), accB=(CV,CVV).
    {
        const float C1F = 6.5025f;    // (0.01*255)^2
        const float C2F = 58.5225f;   // (0.03*255)^2
        const int tx    = tid & 31;
        const int rbase = (tid >> 5) * 4;   // 0,4,...,28

        u64 accA[4], accB[4];
        #pragma unroll
        for (int r = 0; r < 4; r++) { accA[r] = 0ull; accB[r] = 0ull; }

        #pragma unroll
        for (int j = 0; j < 14; j++) {
            int rr = rbase + j;
            float4 v4 = h4[rr * HP4 + tx];
            u64 va = pack2(v4.x, v4.y);
            u64 vb = pack2(v4.z, v4.w);
            #pragma unroll
            for (int r = 0; r < 4; r++) {
                int k = j - r;
                if (k >= 0 && k < 11) {
                    accA[r] = fma2_(w2[KSYM(k)], va, accA[r]);
                    accB[r] = fma2_(w2[KSYM(k)], vb, accB[r]);
                }
            }
        }
        const bool xok = (bx0 + tx) < OUT_DIM;
        #pragma unroll
        for (int r = 0; r < 4; r++) {
            if (xok && (by0 + rbase + r) < OUT_DIM) {
                float cu, cuu, cv, cvv;
                unpack2(accA[r], cu, cuu);
                unpack2(accB[r], cv, cvv);
                float A = cu * cu, B = cv * cv;
                float X = 0.5f * (A - B);       // 2*m1m2
                float Y = 0.5f * (A + B);       // m1^2+m2^2
                float U = 0.5f * (cuu - cvv);   // 2*conv(pt)
                float V = 0.5f * (cuu + cvv);   // conv(pp)+conv(tt)
                float num = (X + C1F) * (U - X + C2F);
                float den = (Y + C1F) * (V - Y + C2F);
                a_ssim += __fdividef(num, den);
            }
        }
    }

    // ---- Phase F: block reduction + atomics -------------------------------
    float comb = fmaf(a_l1, wp.k_l1, fmaf(a_g, wp.k_g, a_rng * wp.k_rng));
    float vals[6] = {comb, a_sp, a_st, a_spp, a_stt, a_ssim};
    #pragma unroll
    for (int q = 0; q < 6; q++) {
        float v = vals[q];
        #pragma unroll
        for (int o = 16; o > 0; o >>= 1) v += __shfl_down_sync(0xffffffffu, v, o);
        vals[q] = v;
    }
    unsigned mm = __reduce_add_sync(0xffffffffu, a_mse);

    int wid = tid >> 5, lane = tid & 31;
    if (lane == 0) {
        #pragma unroll
        for (int q = 0; q < 6; q++) s_redf[wid][q] = vals[q];
        s_redu[wid] = mm;
    }
    __syncthreads();
    if (tid < 32) {
        float v[6];
        #pragma unroll
        for (int q = 0; q < 6; q++) {
            float x = (tid < 8) ? s_redf[tid][q] : 0.f;
            #pragma unroll
            for (int o = 4; o > 0; o >>= 1) x += __shfl_down_sync(0xffffffffu, x, o);
            v[q] = x;
        }
        unsigned xm = (tid < 8) ? s_redu[tid] : 0u;
        #pragma unroll
        for (int o = 4; o > 0; o >>= 1) xm += __shfl_down_sync(0xffffffffu, xm, o);
        if (tid == 0) {
            atomicAdd(&g_comb,  (double)v[0]);
            atomicAdd(&g_sp[b], (double)v[1]);
            atomicAdd(&g_st[b], (double)v[2]);
            atomicAdd(&g_spp[b],(double)v[3]);
            atomicAdd(&g_stt[b],(double)v[4]);
            atomicAdd(&g_ssim,  (double)v[5]);
            atomicAdd(&g_mse[b], (unsigned long long)xm);
        }
    }

    // ---- Tail: last finished block finalizes + resets for next replay -----
    if (tid == 0) {
        __threadfence();
        unsigned prev = atomicAdd(&g_done, 1u);
        s_last = (prev == (unsigned)(NBLOCKS - 1));
    }
    __syncthreads();
    if (s_last && tid == 0) {
        const double n = (double)IMG_H * (double)IMG_W;
        double energy = 0.0, dist = 0.0, psnr = 0.0;
        for (int i = 0; i < NB; i++) {
            double pm = g_sp[i] / n, tm = g_st[i] / n;
            energy += (pm - tm) * (pm - tm);
            double ps = sqrt(fmax((g_spp[i] - n * pm * pm) / (n - 1.0), 0.0));
            double ts = sqrt(fmax((g_stt[i] - n * tm * tm) / (n - 1.0), 0.0));
            dist += (ps - ts) * (ps - ts);
            double mse = (double)g_mse[i] / n;
            psnr += (mse == 0.0) ? 100.0 : 10.0 * log10(65025.0 / mse);
        }
        energy /= NB; dist /= NB; psnr /= NB;
        double ssim_mean = g_ssim / ((double)NB * (double)OUT_DIM * (double)OUT_DIM);
        ssim_mean = fmin(fmax(ssim_mean, 0.0), 1.0);
        double total = g_comb + 0.05 * (energy + 0.5 * dist) + 0.1 * (1.0 - ssim_mean);
        out[0] = (float)total;
        out[1] = (float)psnr;
        out[2] = (float)ssim_mean;

        // reset accumulators so every graph replay starts from a clean state
        g_comb = 0.0; g_ssim = 0.0;
        for (int i = 0; i < NB; i++) {
            g_sp[i] = 0.0; g_st[i] = 0.0; g_spp[i] = 0.0; g_stt[i] = 0.0;
            g_mse[i] = 0ull;
        }
        g_done = 0u;
        __threadfence();
    }
}

extern "C" void kernel_launch(void* const* d_in, const int* in_sizes, int n_in,
                              void* d_out, int out_size)
{
    const float* pred = (const float*)d_in[0];
    const float* targ = (const float*)d_in[1];

    // Gaussian 11-tap (sigma=1.5), normalized in double like the reference
    Wt wv;
    double g[11], s = 0.0;
    for (int i = 0; i < 11; i++) { double d = i - 5.0; g[i] = exp(-(d * d) / 4.5); s += g[i]; }
    for (int i = 0; i < 11; i++) wv.w[i] = (float)(g[i] / s);

    const double n = (double)IMG_H * (double)IMG_W;
    wv.k_l1  = (float)(1.0   / ((double)NB * n));                           // ALPHA*l1
    wv.k_g   = (float)(0.15  / ((double)NB * (double)(IMG_H - 1) * IMG_W)); // BETA*(gh+gw)
    wv.k_rng = (float)(0.005 / ((double)NB * n));                           // GAMMA*0.1*range

    dim3 grid(GRID_X, GRID_Y, NB);
    loss_fused<<<grid, 256>>>(pred, targ, (float*)d_out, wv);
}